// round 1
// baseline (speedup 1.0000x reference)
#include <cuda_runtime.h>
#include <cuda_bf16.h>
#include <math.h>
#include <stdint.h>

// Problem constants
#define BB 2
#define TT 2048
#define CC 1024
#define HH 16
#define DD 64
#define MM (BB*TT)          // 4096
#define N_QKV (3*CC)        // 3072
#define EPSY 1e-6f

// ------------------------- scratch (device globals; no allocs allowed) ----
__device__ float g_qkv[(size_t)MM * N_QKV];   // 50.3 MB
__device__ float g_q[(size_t)MM * CC];
__device__ float g_k[(size_t)MM * CC];
__device__ float g_v[(size_t)MM * CC];
__device__ float g_ao[(size_t)MM * CC];
__device__ float g_xsq[MM];
__device__ float g_xsq2[MM];
__device__ float g_ksqA[N_QKV];
__device__ float g_ksqP[CC];

// ------------------------- column sum-of-squares (k_sq) -------------------
__global__ void colsq_kernel(const float* __restrict__ W, float* __restrict__ out,
                             int K, int N) {
    int n = blockIdx.x * blockDim.x + threadIdx.x;
    if (n >= N) return;
    float s0 = 0.f, s1 = 0.f, s2 = 0.f, s3 = 0.f;
    int k = 0;
    for (; k + 4 <= K; k += 4) {
        float v0 = W[(size_t)(k+0)*N + n];
        float v1 = W[(size_t)(k+1)*N + n];
        float v2 = W[(size_t)(k+2)*N + n];
        float v3 = W[(size_t)(k+3)*N + n];
        s0 += v0*v0; s1 += v1*v1; s2 += v2*v2; s3 += v3*v3;
    }
    for (; k < K; ++k) { float v = W[(size_t)k*N + n]; s0 += v*v; }
    out[n] = (s0 + s1) + (s2 + s3);
}

// ------------------------- row sum-of-squares (x_sq) ----------------------
__global__ void rowsq_kernel(const float* __restrict__ X, float* __restrict__ out,
                             int K) {
    int row = blockIdx.x * blockDim.y + threadIdx.y;
    const float4* p = (const float4*)(X + (size_t)row * K);
    float s = 0.f;
    for (int i = threadIdx.x; i < K/4; i += 32) {
        float4 v = p[i];
        s += v.x*v.x + v.y*v.y + v.z*v.z + v.w*v.w;
    }
    #pragma unroll
    for (int off = 16; off > 0; off >>= 1)
        s += __shfl_xor_sync(0xffffffffu, s, off);
    if (threadIdx.x == 0) out[row] = s;
}

// ------------------------- SGEMM 128x128x8 + YAT epilogue -----------------
// C = A[MxK] @ W[KxN]; out = dot^2/(xsq+ksq-2dot+eps)*scale + bias
#define GBM 128
#define GBN 128
#define GBK 8
__global__ __launch_bounds__(256, 2)
void gemm_yat_kernel(const float* __restrict__ A, const float* __restrict__ W,
                     const float* __restrict__ bias, const float* __restrict__ xsq,
                     const float* __restrict__ ksq, const float* __restrict__ alphap,
                     float* __restrict__ out, int M, int N, int K, float outf) {
    __shared__ float As[2][GBK][GBM];
    __shared__ float Bs[2][GBK][GBN];

    int tid  = threadIdx.x;
    int row0 = blockIdx.y * GBM;
    int col0 = blockIdx.x * GBN;
    int tr = tid >> 4;       // 0..15
    int tc = tid & 15;       // 0..15

    // global load mapping
    int ar = tid >> 1;               // 0..127
    int ak = (tid & 1) * 4;          // 0 or 4
    int br = tid >> 5;               // 0..7
    int bc = (tid & 31) * 4;         // 0..124

    const float* Aptr = A + (size_t)(row0 + ar) * K + ak;
    const float* Bptr = W + (size_t)br * N + col0 + bc;

    float4 ra = *(const float4*)Aptr;
    float4 rb = *(const float4*)Bptr;

    As[0][ak+0][ar] = ra.x;
    As[0][ak+1][ar] = ra.y;
    As[0][ak+2][ar] = ra.z;
    As[0][ak+3][ar] = ra.w;
    *(float4*)&Bs[0][br][bc] = rb;
    __syncthreads();

    float acc[8][8];
    #pragma unroll
    for (int i = 0; i < 8; ++i)
        #pragma unroll
        for (int j = 0; j < 8; ++j) acc[i][j] = 0.f;

    int nk = K / GBK;
    for (int kt = 0; kt < nk; ++kt) {
        int cur = kt & 1;
        if (kt + 1 < nk) {
            ra = *(const float4*)(Aptr + (kt+1) * GBK);
            rb = *(const float4*)(Bptr + (size_t)(kt+1) * GBK * N);
        }
        #pragma unroll
        for (int k = 0; k < GBK; ++k) {
            float af[8], bf[8];
            *(float4*)&af[0] = *(const float4*)&As[cur][k][4*tr];
            *(float4*)&af[4] = *(const float4*)&As[cur][k][64 + 4*tr];
            *(float4*)&bf[0] = *(const float4*)&Bs[cur][k][4*tc];
            *(float4*)&bf[4] = *(const float4*)&Bs[cur][k][64 + 4*tc];
            #pragma unroll
            for (int i = 0; i < 8; ++i)
                #pragma unroll
                for (int j = 0; j < 8; ++j)
                    acc[i][j] += af[i] * bf[j];
        }
        if (kt + 1 < nk) {
            int nxt = cur ^ 1;
            As[nxt][ak+0][ar] = ra.x;
            As[nxt][ak+1][ar] = ra.y;
            As[nxt][ak+2][ar] = ra.z;
            As[nxt][ak+3][ar] = ra.w;
            *(float4*)&Bs[nxt][br][bc] = rb;
            __syncthreads();
        }
    }

    float alpha = *alphap;
    float scl = powf(sqrtf(outf) / logf(1.f + outf), alpha);

    #pragma unroll
    for (int i = 0; i < 8; ++i) {
        int r = row0 + ((i < 4) ? (4*tr + i) : (64 + 4*tr + i - 4));
        float xs = xsq[r];
        #pragma unroll
        for (int j = 0; j < 8; ++j) {
            int cidx = col0 + ((j < 4) ? (4*tc + j) : (64 + 4*tc + j - 4));
            float dot = acc[i][j];
            float dist = xs + ksq[cidx] - 2.f*dot + EPSY;
            out[(size_t)r * N + cidx] = dot * dot / dist * scl + bias[cidx];
        }
    }
}

// ------------------------- RoPE + split/transpose --------------------------
// qkv [B,T,3,H,D] -> q,k (rotary applied), v in [B,H,T,D]
__global__ void rotary_kernel(const float* __restrict__ QKV,
                              float* __restrict__ Qr, float* __restrict__ Kr,
                              float* __restrict__ Vr) {
    int idx = blockIdx.x * blockDim.x + threadIdx.x;   // [b][t][h][d]
    int d = idx & 63;
    int h = (idx >> 6) & 15;
    int t = (idx >> 10) & 2047;
    int b = idx >> 21;

    size_t mrow = (size_t)(b * TT + t) * N_QKV;
    int col = h * DD;

    float v = QKV[mrow + 2*CC + col + d];

    int dd = d & 31;
    bool hi = d >= 32;
    float freq = expf(-logf(10000.f) * ((float)(2*dd) / 64.f));
    float ang = (float)t * freq;
    float sn, cs;
    sincosf(ang, &sn, &cs);

    float q1 = QKV[mrow + col + dd];
    float q2 = QKV[mrow + col + dd + 32];
    float k1 = QKV[mrow + CC + col + dd];
    float k2 = QKV[mrow + CC + col + dd + 32];

    float qv = hi ? (q2*cs + q1*sn) : (q1*cs - q2*sn);
    float kv = hi ? (k2*cs + k1*sn) : (k1*cs - k2*sn);

    size_t o = ((size_t)(b * HH + h) * TT + t) * DD + d;
    Qr[o] = qv;
    Kr[o] = kv;
    Vr[o] = v;
}

// ------------------------- causal flash attention --------------------------
// Q,K,V: [B*H, T, D]; out: [B, T, H*D] (i.e., [M, C])
#define FSTR 68
__global__ __launch_bounds__(256, 3)
void flash_kernel(const float* __restrict__ Q, const float* __restrict__ K,
                  const float* __restrict__ V, float* __restrict__ O) {
    extern __shared__ float sm[];
    float (*Qs)[FSTR] = (float(*)[FSTR])(sm);               // [d][i] transposed
    float (*Ks)[FSTR] = (float(*)[FSTR])(sm + 64*FSTR);     // [d][j] transposed
    float (*Vs)[FSTR] = (float(*)[FSTR])(sm + 2*64*FSTR);   // [j][d]
    float (*Ps)[FSTR] = (float(*)[FSTR])(sm + 3*64*FSTR);   // [i][j]

    int tid = threadIdx.x;
    int bh  = blockIdx.y;
    int q0  = blockIdx.x * 64;
    const float* Qb = Q + (size_t)bh * TT * DD;
    const float* Kb = K + (size_t)bh * TT * DD;
    const float* Vb = V + (size_t)bh * TT * DD;
    int ty = tid >> 4, tx = tid & 15;

    // load Q tile transposed
    #pragma unroll
    for (int it = 0; it < 16; ++it) {
        int idx = tid + it * 256;
        int i = idx >> 6, d = idx & 63;
        Qs[d][i] = Qb[(size_t)(q0 + i) * DD + d];
    }

    float acc[4][4];
    float mrow[4], lrow[4];
    #pragma unroll
    for (int r = 0; r < 4; ++r) {
        mrow[r] = -INFINITY; lrow[r] = 0.f;
        #pragma unroll
        for (int c = 0; c < 4; ++c) acc[r][c] = 0.f;
    }

    int nkt = (q0 >> 6) + 1;
    for (int kt = 0; kt < nkt; ++kt) {
        int k0 = kt * 64;
        __syncthreads();   // Qs visible (kt=0) / prev P·V done before overwrite
        #pragma unroll
        for (int it = 0; it < 16; ++it) {
            int idx = tid + it * 256;
            int i = idx >> 6, d = idx & 63;
            float kvv = Kb[(size_t)(k0 + i) * DD + d];
            float vvv = Vb[(size_t)(k0 + i) * DD + d];
            Ks[d][i] = kvv;
            Vs[i][d] = vvv;
        }
        __syncthreads();

        float s[4][4];
        #pragma unroll
        for (int r = 0; r < 4; ++r)
            #pragma unroll
            for (int c = 0; c < 4; ++c) s[r][c] = 0.f;

        #pragma unroll 8
        for (int d = 0; d < 64; ++d) {
            float qv[4], kv[4];
            *(float4*)qv = *(const float4*)&Qs[d][4*ty];
            *(float4*)kv = *(const float4*)&Ks[d][4*tx];
            #pragma unroll
            for (int r = 0; r < 4; ++r)
                #pragma unroll
                for (int c = 0; c < 4; ++c)
                    s[r][c] += qv[r] * kv[c];
        }

        bool diag = (kt == nkt - 1);
        #pragma unroll
        for (int r = 0; r < 4; ++r) {
            int qg = q0 + 4*ty + r;
            #pragma unroll
            for (int c = 0; c < 4; ++c) {
                s[r][c] *= 0.125f;
                if (diag && (k0 + 4*tx + c) > qg) s[r][c] = -INFINITY;
            }
            float mx = fmaxf(fmaxf(s[r][0], s[r][1]), fmaxf(s[r][2], s[r][3]));
            #pragma unroll
            for (int off = 8; off > 0; off >>= 1)
                mx = fmaxf(mx, __shfl_xor_sync(0xffffffffu, mx, off));
            float mnew = fmaxf(mrow[r], mx);
            float corr = expf(mrow[r] - mnew);
            float rs = 0.f;
            #pragma unroll
            for (int c = 0; c < 4; ++c) {
                float p = expf(s[r][c] - mnew);
                s[r][c] = p;
                rs += p;
            }
            #pragma unroll
            for (int off = 8; off > 0; off >>= 1)
                rs += __shfl_xor_sync(0xffffffffu, rs, off);
            lrow[r] = lrow[r] * corr + rs;
            mrow[r] = mnew;
            #pragma unroll
            for (int c = 0; c < 4; ++c) acc[r][c] *= corr;
        }

        // stage P
        #pragma unroll
        for (int r = 0; r < 4; ++r)
            #pragma unroll
            for (int c = 0; c < 4; ++c)
                Ps[4*ty + r][4*tx + c] = s[r][c];
        __syncthreads();

        // O += P @ V
        #pragma unroll 8
        for (int k = 0; k < 64; ++k) {
            float vv[4];
            *(float4*)vv = *(const float4*)&Vs[k][4*tx];
            float p0 = Ps[4*ty+0][k], p1 = Ps[4*ty+1][k];
            float p2 = Ps[4*ty+2][k], p3 = Ps[4*ty+3][k];
            #pragma unroll
            for (int c = 0; c < 4; ++c) {
                acc[0][c] += p0 * vv[c];
                acc[1][c] += p1 * vv[c];
                acc[2][c] += p2 * vv[c];
                acc[3][c] += p3 * vv[c];
            }
        }
    }

    int b = bh >> 4, h = bh & 15;
    #pragma unroll
    for (int r = 0; r < 4; ++r) {
        float inv = 1.f / lrow[r];
        int t = q0 + 4*ty + r;
        float* op = O + (size_t)(b * TT + t) * CC + h * DD + 4*tx;
        #pragma unroll
        for (int c = 0; c < 4; ++c) op[c] = acc[r][c] * inv;
    }
}

// ------------------------- host launch --------------------------------------
extern "C" void kernel_launch(void* const* d_in, const int* in_sizes, int n_in,
                              void* d_out, int out_size) {
    const float* x      = (const float*)d_in[0];
    // d_in[1] = mask (causal tril; hardcoded in flash kernel)
    const float* w_attn = (const float*)d_in[2];
    const float* b_attn = (const float*)d_in[3];
    const float* a_attn = (const float*)d_in[4];
    const float* w_proj = (const float*)d_in[5];
    const float* b_proj = (const float*)d_in[6];
    const float* a_proj = (const float*)d_in[7];
    float* out = (float*)d_out;

    void *qkv_, *q_, *k_, *v_, *ao_, *xsq_, *xsq2_, *ksqa_, *ksqp_;
    cudaGetSymbolAddress(&qkv_,  g_qkv);
    cudaGetSymbolAddress(&q_,    g_q);
    cudaGetSymbolAddress(&k_,    g_k);
    cudaGetSymbolAddress(&v_,    g_v);
    cudaGetSymbolAddress(&ao_,   g_ao);
    cudaGetSymbolAddress(&xsq_,  g_xsq);
    cudaGetSymbolAddress(&xsq2_, g_xsq2);
    cudaGetSymbolAddress(&ksqa_, g_ksqA);
    cudaGetSymbolAddress(&ksqp_, g_ksqP);
    float* qkv  = (float*)qkv_;
    float* qr   = (float*)q_;
    float* kr   = (float*)k_;
    float* vr   = (float*)v_;
    float* ao   = (float*)ao_;
    float* xsq  = (float*)xsq_;
    float* xsq2 = (float*)xsq2_;
    float* ksqa = (float*)ksqa_;
    float* ksqp = (float*)ksqp_;

    const int fa_smem = 4 * 64 * FSTR * (int)sizeof(float);   // 69632 B
    cudaFuncSetAttribute(flash_kernel, cudaFuncAttributeMaxDynamicSharedMemorySize,
                         fa_smem);

    // k_sq for both weights
    colsq_kernel<<<(N_QKV + 127) / 128, 128>>>(w_attn, ksqa, CC, N_QKV);
    colsq_kernel<<<(CC + 127) / 128, 128>>>(w_proj, ksqp, CC, CC);

    // x_sq
    {
        dim3 blk(32, 8);
        rowsq_kernel<<<MM / 8, blk>>>(x, xsq, CC);
    }

    // GEMM1 + YAT epilogue -> qkv
    {
        dim3 grid(N_QKV / GBN, MM / GBM);
        gemm_yat_kernel<<<grid, 256>>>(x, w_attn, b_attn, xsq, ksqa, a_attn,
                                       qkv, MM, N_QKV, CC, (float)N_QKV);
    }

    // RoPE + split to [B,H,T,D]
    rotary_kernel<<<(MM * CC) / 256, 256>>>(qkv, qr, kr, vr);

    // causal flash attention -> ao [M, C]
    {
        dim3 grid(TT / 64, BB * HH);
        flash_kernel<<<grid, 256, fa_smem>>>(qr, kr, vr, ao);
    }

    // x_sq of attention output
    {
        dim3 blk(32, 8);
        rowsq_kernel<<<MM / 8, blk>>>(ao, xsq2, CC);
    }

    // GEMM2 + YAT epilogue -> out
    {
        dim3 grid(CC / GBN, MM / GBM);
        gemm_yat_kernel<<<grid, 256>>>(ao, w_proj, b_proj, xsq2, ksqp, a_proj,
                                       out, MM, CC, CC, (float)CC);
    }
}

// round 3
// speedup vs baseline: 1.3309x; 1.3309x over previous
#include <cuda_runtime.h>
#include <cuda_bf16.h>
#include <math.h>
#include <stdint.h>

// Problem constants
#define BB 2
#define TT 2048
#define CC 1024
#define HH 16
#define DD 64
#define MM (BB*TT)          // 4096
#define N_QKV (3*CC)        // 3072
#define KK CC               // GEMM K = 1024
#define EPSY 1e-6f

// ------------------------- scratch (device globals) -----------------------
__device__ float g_qkv[(size_t)MM * N_QKV];
__device__ float g_q[(size_t)MM * CC];
__device__ float g_k[(size_t)MM * CC];
__device__ float g_v[(size_t)MM * CC];
__device__ float g_ao[(size_t)MM * CC];
__device__ float g_xsq[MM];
__device__ float g_xsq2[MM];
__device__ float g_ksqA[N_QKV];
__device__ float g_ksqP[CC];
// bf16x2 split planes (A planes reused for x then ao — sequential in graph)
__device__ __nv_bfloat16 g_Ah[(size_t)MM * KK];
__device__ __nv_bfloat16 g_Am[(size_t)MM * KK];
__device__ __nv_bfloat16 g_BhA[(size_t)N_QKV * KK];
__device__ __nv_bfloat16 g_BmA[(size_t)N_QKV * KK];
__device__ __nv_bfloat16 g_BhP[(size_t)CC * KK];
__device__ __nv_bfloat16 g_BmP[(size_t)CC * KK];

// ------------------------- PTX helpers ------------------------------------
__device__ __forceinline__ uint32_t smem_u32(const void* p) {
    uint32_t a;
    asm("{ .reg .u64 t; cvta.to.shared.u64 t, %1; cvt.u32.u64 %0, t; }"
        : "=r"(a) : "l"(p));
    return a;
}
__device__ __forceinline__ void cp16(uint32_t dst, const void* src) {
    asm volatile("cp.async.cg.shared.global [%0], [%1], 16;" :: "r"(dst), "l"(src) : "memory");
}
#define CP_COMMIT() asm volatile("cp.async.commit_group;" ::: "memory")
#define CP_WAIT(n)  asm volatile("cp.async.wait_group %0;" :: "n"(n) : "memory")

#define LDM4(r, addr) \
    asm volatile("ldmatrix.sync.aligned.m8n8.x4.shared.b16 {%0,%1,%2,%3}, [%4];" \
        : "=r"((r)[0]), "=r"((r)[1]), "=r"((r)[2]), "=r"((r)[3]) : "r"(addr))

#define MMA16816(d, a, b) \
    asm volatile("mma.sync.aligned.m16n8k16.row.col.f32.bf16.bf16.f32 " \
        "{%0,%1,%2,%3}, {%4,%5,%6,%7}, {%8,%9}, {%0,%1,%2,%3};" \
        : "+f"((d)[0]), "+f"((d)[1]), "+f"((d)[2]), "+f"((d)[3]) \
        : "r"((a)[0]), "r"((a)[1]), "r"((a)[2]), "r"((a)[3]), \
          "r"((b)[0]), "r"((b)[1]))

// ------------------------- prep kernels -----------------------------------
__global__ void split_kernel(const float* __restrict__ A,
                             __nv_bfloat16* __restrict__ H,
                             __nv_bfloat16* __restrict__ Mp) {
    size_t i = (size_t)blockIdx.x * blockDim.x + threadIdx.x;  // float4 index
    float4 v = ((const float4*)A)[i];
    __nv_bfloat16 h0 = __float2bfloat16(v.x);
    __nv_bfloat16 h1 = __float2bfloat16(v.y);
    __nv_bfloat16 h2 = __float2bfloat16(v.z);
    __nv_bfloat16 h3 = __float2bfloat16(v.w);
    __nv_bfloat16 m0 = __float2bfloat16(v.x - __bfloat162float(h0));
    __nv_bfloat16 m1 = __float2bfloat16(v.y - __bfloat162float(h1));
    __nv_bfloat16 m2 = __float2bfloat16(v.z - __bfloat162float(h2));
    __nv_bfloat16 m3 = __float2bfloat16(v.w - __bfloat162float(h3));
    __nv_bfloat162* Hp = (__nv_bfloat162*)H;
    __nv_bfloat162* Mq = (__nv_bfloat162*)Mp;
    Hp[2*i]   = __nv_bfloat162(h0, h1);
    Hp[2*i+1] = __nv_bfloat162(h2, h3);
    Mq[2*i]   = __nv_bfloat162(m0, m1);
    Mq[2*i+1] = __nv_bfloat162(m2, m3);
}

__global__ void transpose_split_kernel(const float* __restrict__ W,
                                       __nv_bfloat16* __restrict__ Bh,
                                       __nv_bfloat16* __restrict__ Bm, int N) {
    __shared__ float tile[32][33];
    int n0 = blockIdx.x * 32, k0 = blockIdx.y * 32;
    int tx = threadIdx.x, ty = threadIdx.y;
    for (int j = ty; j < 32; j += 8)
        tile[j][tx] = W[(size_t)(k0 + j) * N + n0 + tx];
    __syncthreads();
    for (int j = ty; j < 32; j += 8) {
        float v = tile[tx][j];
        __nv_bfloat16 h = __float2bfloat16(v);
        __nv_bfloat16 m = __float2bfloat16(v - __bfloat162float(h));
        size_t o = (size_t)(n0 + j) * KK + k0 + tx;
        Bh[o] = h; Bm[o] = m;
    }
}

__global__ void colsq_kernel(const float* __restrict__ W, float* __restrict__ out,
                             int K, int N) {
    int n = blockIdx.x * blockDim.x + threadIdx.x;
    if (n >= N) return;
    float s0 = 0.f, s1 = 0.f, s2 = 0.f, s3 = 0.f;
    int k = 0;
    for (; k + 4 <= K; k += 4) {
        float v0 = W[(size_t)(k+0)*N + n];
        float v1 = W[(size_t)(k+1)*N + n];
        float v2 = W[(size_t)(k+2)*N + n];
        float v3 = W[(size_t)(k+3)*N + n];
        s0 += v0*v0; s1 += v1*v1; s2 += v2*v2; s3 += v3*v3;
    }
    out[n] = (s0 + s1) + (s2 + s3);
}

__global__ void rowsq_kernel(const float* __restrict__ X, float* __restrict__ out,
                             int K) {
    int row = blockIdx.x * blockDim.y + threadIdx.y;
    const float4* p = (const float4*)(X + (size_t)row * K);
    float s = 0.f;
    for (int i = threadIdx.x; i < K/4; i += 32) {
        float4 v = p[i];
        s += v.x*v.x + v.y*v.y + v.z*v.z + v.w*v.w;
    }
    #pragma unroll
    for (int off = 16; off > 0; off >>= 1)
        s += __shfl_xor_sync(0xffffffffu, s, off);
    if (threadIdx.x == 0) out[row] = s;
}

// ------------------------- mma.sync GEMM + YAT epilogue -------------------
// out[m][n] = yat( sum_k A[m][k]*W[k][n] ); A split (Ah,Am), W^T split (Bh,Bm).
// CTA 128x128, 8 warps (2x4), warp tile 64x32, K-chunk 32, 2-stage cp.async.
// Smem row: [hi 64B | mid 64B | pad 16B] = 144B.
#define SROW 144
#define GTILE (128*SROW)       // 18432 B per operand tile
#define GSTAGE (2*GTILE)       // 36864 B per stage
#define GNKCH (KK/32)          // 32 chunks

__global__ __launch_bounds__(256, 1)
void gemm_mma_kernel(const __nv_bfloat16* __restrict__ Ah, const __nv_bfloat16* __restrict__ Am,
                     const __nv_bfloat16* __restrict__ Bh, const __nv_bfloat16* __restrict__ Bm,
                     const float* __restrict__ bias, const float* __restrict__ xsq,
                     const float* __restrict__ ksq, const float* __restrict__ alphap,
                     float* __restrict__ out, int N, float outf) {
    extern __shared__ char dsm[];
    uint32_t sbase = smem_u32(dsm);

    const int tid = threadIdx.x;
    const int lane = tid & 31;
    const int wid = tid >> 5;
    const int wm = wid >> 2;          // 0..1  -> m offset 64*wm
    const int wn = wid & 3;           // 0..3  -> n offset 32*wn
    const int m0 = blockIdx.y * 128;
    const int n0 = blockIdx.x * 128;

    const char* pAh = (const char*)Ah + (size_t)m0 * (KK*2);
    const char* pAm = (const char*)Am + (size_t)m0 * (KK*2);
    const char* pBh = (const char*)Bh + (size_t)n0 * (KK*2);
    const char* pBm = (const char*)Bm + (size_t)n0 * (KK*2);

    // per-thread load mapping: 4 iterations cover 128 rows x (2 planes x 4 chunks)
    const int lrow   = tid >> 3;          // +32 per iter... (recomputed below)
    const int lplane = (tid >> 2) & 1;
    const int lchunk = tid & 3;
    (void)lrow;

    #define LOAD_CHUNK(kc, st) do {                                           \
        size_t kb = (size_t)(kc) * 64 + (size_t)lchunk * 16;                  \
        uint32_t sb = sbase + (st) * GSTAGE;                                  \
        _Pragma("unroll")                                                     \
        for (int i = 0; i < 4; ++i) {                                         \
            int row = (tid >> 3) + i * 32;                                    \
            uint32_t doff = row * SROW + lplane * 64 + lchunk * 16;           \
            const char* sa = (lplane ? pAm : pAh) + (size_t)row * (KK*2) + kb;\
            const char* sbp = (lplane ? pBm : pBh) + (size_t)row * (KK*2) + kb;\
            cp16(sb + doff, sa);                                              \
            cp16(sb + GTILE + doff, sbp);                                     \
        }                                                                     \
        CP_COMMIT();                                                          \
    } while (0)

    float acc[4][4][4];
    #pragma unroll
    for (int i = 0; i < 4; ++i)
        #pragma unroll
        for (int j = 0; j < 4; ++j)
            #pragma unroll
            for (int r = 0; r < 4; ++r) acc[i][j][r] = 0.f;

    // A-frag ldmatrix address (within tile): lanes 0-15 -> rows, lanes>=16 -> +8 cols
    const int arow = lane & 15;
    const int akoff = (lane >> 4) * 16;   // bytes
    // B-frag direct LDS address
    const int bn = lane >> 2;             // 0..7
    const int bk = (lane & 3) * 4;        // bytes

    LOAD_CHUNK(0, 0);

    for (int kc = 0; kc < GNKCH; ++kc) {
        int st = kc & 1;
        if (kc + 1 < GNKCH) {
            LOAD_CHUNK(kc + 1, st ^ 1);
            CP_WAIT(1);
        } else {
            CP_WAIT(0);
        }
        __syncthreads();

        uint32_t sA = sbase + st * GSTAGE;
        uint32_t sB = sA + GTILE;

        #pragma unroll
        for (int ks = 0; ks < 2; ++ks) {
            uint32_t a[2][4][4];
            #pragma unroll
            for (int pl = 0; pl < 2; ++pl)
                #pragma unroll
                for (int fm = 0; fm < 4; ++fm) {
                    uint32_t ad = sA + (wm*64 + fm*16 + arow) * SROW
                                + pl*64 + ks*32 + akoff;
                    LDM4(a[pl][fm], ad);
                }
            uint32_t b[2][4][2];
            #pragma unroll
            for (int pl = 0; pl < 2; ++pl)
                #pragma unroll
                for (int fn = 0; fn < 4; ++fn) {
                    uint32_t bd = sB + (wn*32 + fn*8 + bn) * SROW
                                + pl*64 + ks*32 + bk;
                    asm volatile("ld.shared.b32 %0, [%1];" : "=r"(b[pl][fn][0]) : "r"(bd));
                    asm volatile("ld.shared.b32 %0, [%1];" : "=r"(b[pl][fn][1]) : "r"(bd + 16));
                }
            #pragma unroll
            for (int fm = 0; fm < 4; ++fm)
                #pragma unroll
                for (int fn = 0; fn < 4; ++fn) {
                    MMA16816(acc[fm][fn], a[0][fm], b[0][fn]);   // hh
                    MMA16816(acc[fm][fn], a[0][fm], b[1][fn]);   // h*m
                    MMA16816(acc[fm][fn], a[1][fm], b[0][fn]);   // m*h
                }
        }
        __syncthreads();
    }

    // -------- YAT epilogue ---------------------------------------------------
    float alpha = *alphap;
    float scl = powf(sqrtf(outf) / logf(1.f + outf), alpha);
    int g = lane >> 2;
    int t2 = (lane & 3) * 2;

    #pragma unroll
    for (int fm = 0; fm < 4; ++fm) {
        int mA = m0 + wm*64 + fm*16 + g;
        float xsA = xsq[mA];
        float xsB = xsq[mA + 8];
        #pragma unroll
        for (int fn = 0; fn < 4; ++fn) {
            int col = n0 + wn*32 + fn*8 + t2;
            float k0v = ksq[col], k1v = ksq[col+1];
            float b0v = bias[col], b1v = bias[col+1];
            float d0 = acc[fm][fn][0], d1 = acc[fm][fn][1];
            float d2 = acc[fm][fn][2], d3 = acc[fm][fn][3];
            float2 o01, o23;
            o01.x = d0*d0 / (xsA + k0v - 2.f*d0 + EPSY) * scl + b0v;
            o01.y = d1*d1 / (xsA + k1v - 2.f*d1 + EPSY) * scl + b1v;
            o23.x = d2*d2 / (xsB + k0v - 2.f*d2 + EPSY) * scl + b0v;
            o23.y = d3*d3 / (xsB + k1v - 2.f*d3 + EPSY) * scl + b1v;
            *(float2*)(out + (size_t)mA * N + col) = o01;
            *(float2*)(out + (size_t)(mA + 8) * N + col) = o23;
        }
    }
    #undef LOAD_CHUNK
}

// ------------------------- RoPE + split/transpose --------------------------
__global__ void rotary_kernel(const float* __restrict__ QKV,
                              float* __restrict__ Qr, float* __restrict__ Kr,
                              float* __restrict__ Vr) {
    int idx = blockIdx.x * blockDim.x + threadIdx.x;
    int d = idx & 63;
    int h = (idx >> 6) & 15;
    int t = (idx >> 10) & 2047;
    int b = idx >> 21;

    size_t mrow = (size_t)(b * TT + t) * N_QKV;
    int col = h * DD;
    float v = QKV[mrow + 2*CC + col + d];

    int dd = d & 31;
    bool hi = d >= 32;
    float freq = expf(-logf(10000.f) * ((float)(2*dd) / 64.f));
    float ang = (float)t * freq;
    float sn, cs;
    sincosf(ang, &sn, &cs);

    float q1 = QKV[mrow + col + dd];
    float q2 = QKV[mrow + col + dd + 32];
    float k1 = QKV[mrow + CC + col + dd];
    float k2 = QKV[mrow + CC + col + dd + 32];

    float qv = hi ? (q2*cs + q1*sn) : (q1*cs - q2*sn);
    float kv = hi ? (k2*cs + k1*sn) : (k1*cs - k2*sn);

    size_t o = ((size_t)(b * HH + h) * TT + t) * DD + d;
    Qr[o] = qv;
    Kr[o] = kv;
    Vr[o] = v;
}

// ------------------------- causal flash attention --------------------------
#define FSTR 68
__global__ __launch_bounds__(256, 3)
void flash_kernel(const float* __restrict__ Q, const float* __restrict__ K,
                  const float* __restrict__ V, float* __restrict__ O) {
    extern __shared__ float sm[];
    float (*Qs)[FSTR] = (float(*)[FSTR])(sm);
    float (*Ks)[FSTR] = (float(*)[FSTR])(sm + 64*FSTR);
    float (*Vs)[FSTR] = (float(*)[FSTR])(sm + 2*64*FSTR);
    float (*Ps)[FSTR] = (float(*)[FSTR])(sm + 3*64*FSTR);

    int tid = threadIdx.x;
    int bh  = blockIdx.y;
    int q0  = blockIdx.x * 64;
    const float* Qb = Q + (size_t)bh * TT * DD;
    const float* Kb = K + (size_t)bh * TT * DD;
    const float* Vb = V + (size_t)bh * TT * DD;
    int ty = tid >> 4, tx = tid & 15;

    #pragma unroll
    for (int it = 0; it < 16; ++it) {
        int idx = tid + it * 256;
        int i = idx >> 6, d = idx & 63;
        Qs[d][i] = Qb[(size_t)(q0 + i) * DD + d];
    }

    float acc[4][4];
    float mrow[4], lrow[4];
    #pragma unroll
    for (int r = 0; r < 4; ++r) {
        mrow[r] = -INFINITY; lrow[r] = 0.f;
        #pragma unroll
        for (int c = 0; c < 4; ++c) acc[r][c] = 0.f;
    }

    int nkt = (q0 >> 6) + 1;
    for (int kt = 0; kt < nkt; ++kt) {
        int k0 = kt * 64;
        __syncthreads();
        #pragma unroll
        for (int it = 0; it < 16; ++it) {
            int idx = tid + it * 256;
            int i = idx >> 6, d = idx & 63;
            Ks[d][i] = Kb[(size_t)(k0 + i) * DD + d];
            Vs[i][d] = Vb[(size_t)(k0 + i) * DD + d];
        }
        __syncthreads();

        float s[4][4];
        #pragma unroll
        for (int r = 0; r < 4; ++r)
            #pragma unroll
            for (int c = 0; c < 4; ++c) s[r][c] = 0.f;

        #pragma unroll 8
        for (int d = 0; d < 64; ++d) {
            float qv[4], kv[4];
            *(float4*)qv = *(const float4*)&Qs[d][4*ty];
            *(float4*)kv = *(const float4*)&Ks[d][4*tx];
            #pragma unroll
            for (int r = 0; r < 4; ++r)
                #pragma unroll
                for (int c = 0; c < 4; ++c)
                    s[r][c] += qv[r] * kv[c];
        }

        bool diag = (kt == nkt - 1);
        #pragma unroll
        for (int r = 0; r < 4; ++r) {
            int qg = q0 + 4*ty + r;
            #pragma unroll
            for (int c = 0; c < 4; ++c) {
                s[r][c] *= 0.125f;
                if (diag && (k0 + 4*tx + c) > qg) s[r][c] = -INFINITY;
            }
            float mx = fmaxf(fmaxf(s[r][0], s[r][1]), fmaxf(s[r][2], s[r][3]));
            #pragma unroll
            for (int off = 8; off > 0; off >>= 1)
                mx = fmaxf(mx, __shfl_xor_sync(0xffffffffu, mx, off));
            float mnew = fmaxf(mrow[r], mx);
            float corr = expf(mrow[r] - mnew);
            float rs = 0.f;
            #pragma unroll
            for (int c = 0; c < 4; ++c) {
                float p = expf(s[r][c] - mnew);
                s[r][c] = p;
                rs += p;
            }
            #pragma unroll
            for (int off = 8; off > 0; off >>= 1)
                rs += __shfl_xor_sync(0xffffffffu, rs, off);
            lrow[r] = lrow[r] * corr + rs;
            mrow[r] = mnew;
            #pragma unroll
            for (int c = 0; c < 4; ++c) acc[r][c] *= corr;
        }

        #pragma unroll
        for (int r = 0; r < 4; ++r)
            #pragma unroll
            for (int c = 0; c < 4; ++c)
                Ps[4*ty + r][4*tx + c] = s[r][c];
        __syncthreads();

        #pragma unroll 8
        for (int k = 0; k < 64; ++k) {
            float vv[4];
            *(float4*)vv = *(const float4*)&Vs[k][4*tx];
            float p0 = Ps[4*ty+0][k], p1 = Ps[4*ty+1][k];
            float p2 = Ps[4*ty+2][k], p3 = Ps[4*ty+3][k];
            #pragma unroll
            for (int c = 0; c < 4; ++c) {
                acc[0][c] += p0 * vv[c];
                acc[1][c] += p1 * vv[c];
                acc[2][c] += p2 * vv[c];
                acc[3][c] += p3 * vv[c];
            }
        }
    }

    int b = bh >> 4, h = bh & 15;
    #pragma unroll
    for (int r = 0; r < 4; ++r) {
        float inv = 1.f / lrow[r];
        int t = q0 + 4*ty + r;
        float* op = O + (size_t)(b * TT + t) * CC + h * DD + 4*tx;
        #pragma unroll
        for (int c = 0; c < 4; ++c) op[c] = acc[r][c] * inv;
    }
}

// ------------------------- host launch --------------------------------------
extern "C" void kernel_launch(void* const* d_in, const int* in_sizes, int n_in,
                              void* d_out, int out_size) {
    const float* x      = (const float*)d_in[0];
    const float* w_attn = (const float*)d_in[2];
    const float* b_attn = (const float*)d_in[3];
    const float* a_attn = (const float*)d_in[4];
    const float* w_proj = (const float*)d_in[5];
    const float* b_proj = (const float*)d_in[6];
    const float* a_proj = (const float*)d_in[7];
    float* out = (float*)d_out;

    void *qkv_, *q_, *k_, *v_, *ao_, *xsq_, *xsq2_, *ksqa_, *ksqp_;
    void *ah_, *am_, *bha_, *bma_, *bhp_, *bmp_;
    cudaGetSymbolAddress(&qkv_,  g_qkv);
    cudaGetSymbolAddress(&q_,    g_q);
    cudaGetSymbolAddress(&k_,    g_k);
    cudaGetSymbolAddress(&v_,    g_v);
    cudaGetSymbolAddress(&ao_,   g_ao);
    cudaGetSymbolAddress(&xsq_,  g_xsq);
    cudaGetSymbolAddress(&xsq2_, g_xsq2);
    cudaGetSymbolAddress(&ksqa_, g_ksqA);
    cudaGetSymbolAddress(&ksqp_, g_ksqP);
    cudaGetSymbolAddress(&ah_,   g_Ah);
    cudaGetSymbolAddress(&am_,   g_Am);
    cudaGetSymbolAddress(&bha_,  g_BhA);
    cudaGetSymbolAddress(&bma_,  g_BmA);
    cudaGetSymbolAddress(&bhp_,  g_BhP);
    cudaGetSymbolAddress(&bmp_,  g_BmP);
    float* qkv  = (float*)qkv_;
    float* qr   = (float*)q_;
    float* kr   = (float*)k_;
    float* vr   = (float*)v_;
    float* ao   = (float*)ao_;
    float* xsq  = (float*)xsq_;
    float* xsq2 = (float*)xsq2_;
    float* ksqa = (float*)ksqa_;
    float* ksqp = (float*)ksqp_;
    __nv_bfloat16* Ah  = (__nv_bfloat16*)ah_;
    __nv_bfloat16* Am  = (__nv_bfloat16*)am_;
    __nv_bfloat16* BhA = (__nv_bfloat16*)bha_;
    __nv_bfloat16* BmA = (__nv_bfloat16*)bma_;
    __nv_bfloat16* BhP = (__nv_bfloat16*)bhp_;
    __nv_bfloat16* BmP = (__nv_bfloat16*)bmp_;

    const int gemm_smem = 2 * GSTAGE;                        // 73728
    cudaFuncSetAttribute(gemm_mma_kernel,
                         cudaFuncAttributeMaxDynamicSharedMemorySize, gemm_smem);
    const int fa_smem = 4 * 64 * FSTR * (int)sizeof(float);  // 69632
    cudaFuncSetAttribute(flash_kernel,
                         cudaFuncAttributeMaxDynamicSharedMemorySize, fa_smem);

    // prep: splits, transposes, norms
    split_kernel<<<(MM * KK / 4) / 256, 256>>>(x, Ah, Am);
    {
        dim3 g(N_QKV/32, KK/32), b(32, 8);
        transpose_split_kernel<<<g, b>>>(w_attn, BhA, BmA, N_QKV);
    }
    {
        dim3 g(CC/32, KK/32), b(32, 8);
        transpose_split_kernel<<<g, b>>>(w_proj, BhP, BmP, CC);
    }
    colsq_kernel<<<(N_QKV + 127) / 128, 128>>>(w_attn, ksqa, CC, N_QKV);
    colsq_kernel<<<(CC + 127) / 128, 128>>>(w_proj, ksqp, CC, CC);
    {
        dim3 blk(32, 8);
        rowsq_kernel<<<MM / 8, blk>>>(x, xsq, CC);
    }

    // GEMM1 (mma.sync bf16x2) + YAT -> qkv
    {
        dim3 grid(N_QKV / 128, MM / 128);
        gemm_mma_kernel<<<grid, 256, gemm_smem>>>(Ah, Am, BhA, BmA, b_attn, xsq,
                                                  ksqa, a_attn, qkv, N_QKV,
                                                  (float)N_QKV);
    }

    rotary_kernel<<<(MM * CC) / 256, 256>>>(qkv, qr, kr, vr);

    {
        dim3 grid(TT / 64, BB * HH);
        flash_kernel<<<grid, 256, fa_smem>>>(qr, kr, vr, ao);
    }

    {
        dim3 blk(32, 8);
        rowsq_kernel<<<MM / 8, blk>>>(ao, xsq2, CC);
    }
    split_kernel<<<(MM * KK / 4) / 256, 256>>>(ao, Ah, Am);

    // GEMM2 (mma.sync bf16x2) + YAT -> out
    {
        dim3 grid(CC / 128, MM / 128);
        gemm_mma_kernel<<<grid, 256, gemm_smem>>>(Ah, Am, BhP, BmP, b_proj, xsq2,
                                                  ksqp, a_proj, out, CC,
                                                  (float)CC);
    }
}

// round 4
// speedup vs baseline: 2.3001x; 1.7282x over previous
#include <cuda_runtime.h>
#include <cuda_bf16.h>
#include <math.h>
#include <stdint.h>

// Problem constants
#define BB 2
#define TT 2048
#define CC 1024
#define HH 16
#define DD 64
#define MM (BB*TT)          // 4096
#define N_QKV (3*CC)        // 3072
#define KK CC               // GEMM K = 1024
#define BH (BB*HH)          // 32
#define EPSY 1e-6f

// ------------------------- scratch (device globals) -----------------------
__device__ float g_qkv[(size_t)MM * N_QKV];
__device__ float g_ao[(size_t)MM * CC];
__device__ float g_xsq[MM];
__device__ float g_xsq2[MM];
__device__ float g_ksqA[N_QKV];
__device__ float g_ksqP[CC];
__device__ __nv_bfloat16 g_Ah[(size_t)MM * KK];
__device__ __nv_bfloat16 g_Am[(size_t)MM * KK];
__device__ __nv_bfloat16 g_BhA[(size_t)N_QKV * KK];
__device__ __nv_bfloat16 g_BmA[(size_t)N_QKV * KK];
__device__ __nv_bfloat16 g_BhP[(size_t)CC * KK];
__device__ __nv_bfloat16 g_BmP[(size_t)CC * KK];
// flash operands: Qp/Kp [bh][t][hi(64)|mid(64)] bf16; Vt [bh][plane(2)][d(64)][T]
__device__ __nv_bfloat16 g_Qp[(size_t)BH * TT * 128];
__device__ __nv_bfloat16 g_Kp[(size_t)BH * TT * 128];
__device__ __nv_bfloat16 g_Vt[(size_t)BH * 128 * TT];

// ------------------------- PTX helpers ------------------------------------
__device__ __forceinline__ uint32_t smem_u32(const void* p) {
    uint32_t a;
    asm("{ .reg .u64 t; cvta.to.shared.u64 t, %1; cvt.u32.u64 %0, t; }"
        : "=r"(a) : "l"(p));
    return a;
}
__device__ __forceinline__ void cp16(uint32_t dst, const void* src) {
    asm volatile("cp.async.cg.shared.global [%0], [%1], 16;" :: "r"(dst), "l"(src) : "memory");
}
#define CP_COMMIT() asm volatile("cp.async.commit_group;" ::: "memory")
#define CP_WAIT(n)  asm volatile("cp.async.wait_group %0;" :: "n"(n) : "memory")

#define LDM4(r, addr) \
    asm volatile("ldmatrix.sync.aligned.m8n8.x4.shared.b16 {%0,%1,%2,%3}, [%4];" \
        : "=r"((r)[0]), "=r"((r)[1]), "=r"((r)[2]), "=r"((r)[3]) : "r"(addr))

#define MMA16816(d, a, b) \
    asm volatile("mma.sync.aligned.m16n8k16.row.col.f32.bf16.bf16.f32 " \
        "{%0,%1,%2,%3}, {%4,%5,%6,%7}, {%8,%9}, {%0,%1,%2,%3};" \
        : "+f"((d)[0]), "+f"((d)[1]), "+f"((d)[2]), "+f"((d)[3]) \
        : "r"((a)[0]), "r"((a)[1]), "r"((a)[2]), "r"((a)[3]), \
          "r"((b)[0]), "r"((b)[1]))

__device__ __forceinline__ uint32_t lds32(uint32_t a) {
    uint32_t v;
    asm volatile("ld.shared.b32 %0, [%1];" : "=r"(v) : "r"(a));
    return v;
}
// packs {hi, lo} fp32 -> bf16x2 (first source is upper half)
__device__ __forceinline__ uint32_t pack_bf16x2(float hi, float lo) {
    uint32_t r;
    asm("cvt.rn.bf16x2.f32 %0, %1, %2;" : "=r"(r) : "f"(hi), "f"(lo));
    return r;
}

// ------------------------- prep kernels -----------------------------------
// bf16x2 split + fused row sum-of-squares (one block == one 1024-float row)
__global__ void split2_kernel(const float* __restrict__ A,
                              __nv_bfloat16* __restrict__ H,
                              __nv_bfloat16* __restrict__ Mp,
                              float* __restrict__ xsq) {
    __shared__ float red[8];
    int row = blockIdx.x, tid = threadIdx.x;
    size_t i = (size_t)row * 256 + tid;
    float4 v = ((const float4*)A)[i];
    __nv_bfloat16 h0 = __float2bfloat16(v.x);
    __nv_bfloat16 h1 = __float2bfloat16(v.y);
    __nv_bfloat16 h2 = __float2bfloat16(v.z);
    __nv_bfloat16 h3 = __float2bfloat16(v.w);
    __nv_bfloat162* Hp = (__nv_bfloat162*)H;
    __nv_bfloat162* Mq = (__nv_bfloat162*)Mp;
    Hp[2*i]   = __nv_bfloat162(h0, h1);
    Hp[2*i+1] = __nv_bfloat162(h2, h3);
    Mq[2*i]   = __nv_bfloat162(__float2bfloat16(v.x - __bfloat162float(h0)),
                               __float2bfloat16(v.y - __bfloat162float(h1)));
    Mq[2*i+1] = __nv_bfloat162(__float2bfloat16(v.z - __bfloat162float(h2)),
                               __float2bfloat16(v.w - __bfloat162float(h3)));
    float s = v.x*v.x + v.y*v.y + v.z*v.z + v.w*v.w;
    #pragma unroll
    for (int off = 16; off > 0; off >>= 1)
        s += __shfl_xor_sync(0xffffffffu, s, off);
    if ((tid & 31) == 0) red[tid >> 5] = s;
    __syncthreads();
    if (tid == 0) {
        float t = 0.f;
        #pragma unroll
        for (int w = 0; w < 8; ++w) t += red[w];
        xsq[row] = t;
    }
}

__global__ void zero_kernel(float* __restrict__ a, int n) {
    int i = blockIdx.x * 256 + threadIdx.x;
    if (i < n) a[i] = 0.f;
}

// W [K,N] -> W^T split planes [N,K]; fused column sum-of-squares via atomics
__global__ void transpose_split_kernel(const float* __restrict__ W,
                                       __nv_bfloat16* __restrict__ Bh,
                                       __nv_bfloat16* __restrict__ Bm,
                                       float* __restrict__ ksq, int N) {
    __shared__ float tile[32][33];
    int n0 = blockIdx.x * 32, k0 = blockIdx.y * 32;
    int tx = threadIdx.x, ty = threadIdx.y;
    for (int j = ty; j < 32; j += 8)
        tile[j][tx] = W[(size_t)(k0 + j) * N + n0 + tx];
    __syncthreads();
    for (int j = ty; j < 32; j += 8) {
        float v = tile[tx][j];
        __nv_bfloat16 h = __float2bfloat16(v);
        __nv_bfloat16 m = __float2bfloat16(v - __bfloat162float(h));
        size_t o = (size_t)(n0 + j) * KK + k0 + tx;
        Bh[o] = h; Bm[o] = m;
        float sq = v * v;
        #pragma unroll
        for (int off = 16; off > 0; off >>= 1)
            sq += __shfl_xor_sync(0xffffffffu, sq, off);
        if (tx == 0) atomicAdd(&ksq[n0 + j], sq);
    }
}

// ------------------------- mma.sync GEMM + YAT epilogue -------------------
#define SROW 144
#define GTILE (128*SROW)
#define GSTAGE (2*GTILE)
#define GNKCH (KK/32)

__global__ __launch_bounds__(256, 1)
void gemm_mma_kernel(const __nv_bfloat16* __restrict__ Ah, const __nv_bfloat16* __restrict__ Am,
                     const __nv_bfloat16* __restrict__ Bh, const __nv_bfloat16* __restrict__ Bm,
                     const float* __restrict__ bias, const float* __restrict__ xsq,
                     const float* __restrict__ ksq, const float* __restrict__ alphap,
                     float* __restrict__ out, int N, float outf) {
    extern __shared__ char dsm[];
    uint32_t sbase = smem_u32(dsm);

    const int tid = threadIdx.x;
    const int lane = tid & 31;
    const int wid = tid >> 5;
    const int wm = wid >> 2;
    const int wn = wid & 3;
    const int m0 = blockIdx.y * 128;
    const int n0 = blockIdx.x * 128;

    const char* pAh = (const char*)Ah + (size_t)m0 * (KK*2);
    const char* pAm = (const char*)Am + (size_t)m0 * (KK*2);
    const char* pBh = (const char*)Bh + (size_t)n0 * (KK*2);
    const char* pBm = (const char*)Bm + (size_t)n0 * (KK*2);

    const int lplane = (tid >> 2) & 1;
    const int lchunk = tid & 3;

    #define LOAD_CHUNK(kc, st) do {                                           \
        size_t kb = (size_t)(kc) * 64 + (size_t)lchunk * 16;                  \
        uint32_t sb = sbase + (st) * GSTAGE;                                  \
        _Pragma("unroll")                                                     \
        for (int i = 0; i < 4; ++i) {                                         \
            int row = (tid >> 3) + i * 32;                                    \
            uint32_t doff = row * SROW + lplane * 64 + lchunk * 16;           \
            const char* sa = (lplane ? pAm : pAh) + (size_t)row * (KK*2) + kb;\
            const char* sbp = (lplane ? pBm : pBh) + (size_t)row * (KK*2) + kb;\
            cp16(sb + doff, sa);                                              \
            cp16(sb + GTILE + doff, sbp);                                     \
        }                                                                     \
        CP_COMMIT();                                                          \
    } while (0)

    float acc[4][4][4];
    #pragma unroll
    for (int i = 0; i < 4; ++i)
        #pragma unroll
        for (int j = 0; j < 4; ++j)
            #pragma unroll
            for (int r = 0; r < 4; ++r) acc[i][j][r] = 0.f;

    const int arow = lane & 15;
    const int akoff = (lane >> 4) * 16;
    const int bn = lane >> 2;
    const int bk = (lane & 3) * 4;

    LOAD_CHUNK(0, 0);

    for (int kc = 0; kc < GNKCH; ++kc) {
        int st = kc & 1;
        if (kc + 1 < GNKCH) {
            LOAD_CHUNK(kc + 1, st ^ 1);
            CP_WAIT(1);
        } else {
            CP_WAIT(0);
        }
        __syncthreads();

        uint32_t sA = sbase + st * GSTAGE;
        uint32_t sB = sA + GTILE;

        #pragma unroll
        for (int ks = 0; ks < 2; ++ks) {
            uint32_t a[2][4][4];
            #pragma unroll
            for (int pl = 0; pl < 2; ++pl)
                #pragma unroll
                for (int fm = 0; fm < 4; ++fm) {
                    uint32_t ad = sA + (wm*64 + fm*16 + arow) * SROW
                                + pl*64 + ks*32 + akoff;
                    LDM4(a[pl][fm], ad);
                }
            uint32_t b[2][4][2];
            #pragma unroll
            for (int pl = 0; pl < 2; ++pl)
                #pragma unroll
                for (int fn = 0; fn < 4; ++fn) {
                    uint32_t bd = sB + (wn*32 + fn*8 + bn) * SROW
                                + pl*64 + ks*32 + bk;
                    b[pl][fn][0] = lds32(bd);
                    b[pl][fn][1] = lds32(bd + 16);
                }
            #pragma unroll
            for (int fm = 0; fm < 4; ++fm)
                #pragma unroll
                for (int fn = 0; fn < 4; ++fn) {
                    MMA16816(acc[fm][fn], a[0][fm], b[0][fn]);
                    MMA16816(acc[fm][fn], a[0][fm], b[1][fn]);
                    MMA16816(acc[fm][fn], a[1][fm], b[0][fn]);
                }
        }
        __syncthreads();
    }

    float alpha = *alphap;
    float scl = powf(sqrtf(outf) / logf(1.f + outf), alpha);
    int g = lane >> 2;
    int t2 = (lane & 3) * 2;

    #pragma unroll
    for (int fm = 0; fm < 4; ++fm) {
        int mA = m0 + wm*64 + fm*16 + g;
        float xsA = xsq[mA];
        float xsB = xsq[mA + 8];
        #pragma unroll
        for (int fn = 0; fn < 4; ++fn) {
            int col = n0 + wn*32 + fn*8 + t2;
            float k0v = ksq[col], k1v = ksq[col+1];
            float b0v = bias[col], b1v = bias[col+1];
            float d0 = acc[fm][fn][0], d1 = acc[fm][fn][1];
            float d2 = acc[fm][fn][2], d3 = acc[fm][fn][3];
            float2 o01, o23;
            o01.x = d0*d0 / (xsA + k0v - 2.f*d0 + EPSY) * scl + b0v;
            o01.y = d1*d1 / (xsA + k1v - 2.f*d1 + EPSY) * scl + b1v;
            o23.x = d2*d2 / (xsB + k0v - 2.f*d2 + EPSY) * scl + b0v;
            o23.y = d3*d3 / (xsB + k1v - 2.f*d3 + EPSY) * scl + b1v;
            *(float2*)(out + (size_t)mA * N + col) = o01;
            *(float2*)(out + (size_t)(mA + 8) * N + col) = o23;
        }
    }
    #undef LOAD_CHUNK
}

// ------------------------- RoPE + bf16x2 split + V transpose ---------------
// block: 64 t x 64 d of one (b,h). Q scaled by 1/sqrt(D)=0.125 here.
__global__ __launch_bounds__(256)
void rotary2_kernel(const float* __restrict__ QKV,
                    __nv_bfloat16* __restrict__ Qp,
                    __nv_bfloat16* __restrict__ Kp,
                    __nv_bfloat16* __restrict__ Vt) {
    __shared__ __nv_bfloat16 vt[128][66];
    int tid = threadIdx.x;
    int bh = blockIdx.y;
    int t0 = blockIdx.x * 64;
    int b = bh >> 4, h = bh & 15;
    #pragma unroll
    for (int i = 0; i < 16; ++i) {
        int idx = tid + i * 256;
        int t = idx >> 6, d = idx & 63;
        int tg = t0 + t;
        size_t base = (size_t)(b * TT + tg) * N_QKV + h * 64;
        int dd = d & 31;
        bool hi = d >= 32;
        float freq = expf(-9.2103403719761836f * ((float)(2*dd) / 64.f));
        float sn, cs;
        sincosf((float)tg * freq, &sn, &cs);
        float q1 = QKV[base + dd],      q2 = QKV[base + dd + 32];
        float k1 = QKV[base + CC + dd], k2 = QKV[base + CC + dd + 32];
        float v  = QKV[base + 2*CC + d];
        float qv = (hi ? (q2*cs + q1*sn) : (q1*cs - q2*sn)) * 0.125f;
        float kv =  hi ? (k2*cs + k1*sn) : (k1*cs - k2*sn);
        __nv_bfloat16 qh = __float2bfloat16(qv);
        __nv_bfloat16 kh = __float2bfloat16(kv);
        size_t orow = ((size_t)bh * TT + tg) * 128;
        Qp[orow + d]      = qh;
        Qp[orow + 64 + d] = __float2bfloat16(qv - __bfloat162float(qh));
        Kp[orow + d]      = kh;
        Kp[orow + 64 + d] = __float2bfloat16(kv - __bfloat162float(kh));
        __nv_bfloat16 vh = __float2bfloat16(v);
        vt[d][t]      = vh;
        vt[64 + d][t] = __float2bfloat16(v - __bfloat162float(vh));
    }
    __syncthreads();
    uint32_t* outp = (uint32_t*)Vt;
    const uint32_t* vts = (const uint32_t*)&vt[0][0];
    #pragma unroll
    for (int i = 0; i < 16; ++i) {
        int idx = tid + i * 256;
        int r = idx >> 5, cpos = idx & 31;
        outp[((size_t)bh * 128 + r) * 1024 + (t0 >> 1) + cpos] = vts[r * 33 + cpos];
    }
}

// ------------------------- flash attention (mma.sync, bf16x2) --------------
// BQ=128, BK=64, 8 warps x 16 q rows. Q/K rows: [hi128|mid128|pad16]=272B.
// Vt rows (plane*64+d): 64 seq bf16 = 128B, padded stride 144B.
#define FQ 128
#define QROW 272
#define VROW 144
#define SQ_SZ (128*QROW)                 // 34816
#define SK_OFF SQ_SZ
#define SK_SZ (64*QROW)                  // 17408
#define SV_OFF (SK_OFF + 2*SK_SZ)        // 69632
#define SV_SZ (128*VROW)                 // 18432
#define FSMEM (SV_OFF + 2*SV_SZ)         // 106496

__global__ __launch_bounds__(256, 1)
void flash_mma_kernel(const __nv_bfloat16* __restrict__ Qp,
                      const __nv_bfloat16* __restrict__ Kp,
                      const __nv_bfloat16* __restrict__ Vt,
                      float* __restrict__ O) {
    extern __shared__ char smf[];
    uint32_t sb = smem_u32(smf);
    int tid = threadIdx.x;
    int lane = tid & 31, wq = tid >> 5;
    int bh = blockIdx.y;
    int q0 = ((int)gridDim.x - 1 - (int)blockIdx.x) * FQ;   // big tiles first
    const char* Qg = (const char*)(Qp + ((size_t)bh * TT + q0) * 128);
    const char* Kg = (const char*)(Kp + (size_t)bh * TT * 128);
    const char* Vg = (const char*)(Vt + (size_t)bh * 128 * TT);

    // Q tile + KV tile 0 -> group 0
    #pragma unroll
    for (int i = 0; i < 8; ++i) {
        int idx = tid + i * 256; int r = idx >> 4, ch = idx & 15;
        cp16(sb + r * QROW + ch * 16, Qg + (size_t)r * 256 + ch * 16);
    }
    #pragma unroll
    for (int i = 0; i < 4; ++i) {
        int idx = tid + i * 256; int r = idx >> 4, ch = idx & 15;
        cp16(sb + SK_OFF + r * QROW + ch * 16, Kg + (size_t)r * 256 + ch * 16);
    }
    #pragma unroll
    for (int i = 0; i < 4; ++i) {
        int idx = tid + i * 256; int r = idx >> 3, ch = idx & 7;
        cp16(sb + SV_OFF + r * VROW + ch * 16, Vg + (size_t)r * 4096 + ch * 16);
    }
    CP_COMMIT();

    float oacc[8][4];
    #pragma unroll
    for (int fo = 0; fo < 8; ++fo)
        #pragma unroll
        for (int r = 0; r < 4; ++r) oacc[fo][r] = 0.f;
    uint32_t qa[2][4][4];
    float l0 = 0.f, l1 = 0.f, m0 = -1e30f, m1 = -1e30f;
    const int g = lane >> 2, cq = lane & 3;
    const int nkt = q0 / 64 + 2;

    for (int kt = 0; kt < nkt; ++kt) {
        int st = kt & 1;
        if (kt + 1 < nkt) {
            int sn = st ^ 1, k0n = (kt + 1) * 64;
            #pragma unroll
            for (int i = 0; i < 4; ++i) {
                int idx = tid + i * 256; int r = idx >> 4, ch = idx & 15;
                cp16(sb + SK_OFF + sn * SK_SZ + r * QROW + ch * 16,
                     Kg + (size_t)(k0n + r) * 256 + ch * 16);
            }
            #pragma unroll
            for (int i = 0; i < 4; ++i) {
                int idx = tid + i * 256; int r = idx >> 3, ch = idx & 7;
                cp16(sb + SV_OFF + sn * SV_SZ + r * VROW + ch * 16,
                     Vg + (size_t)r * 4096 + (size_t)k0n * 2 + ch * 16);
            }
            CP_COMMIT();
            CP_WAIT(1);
        } else {
            CP_WAIT(0);
        }
        __syncthreads();

        if (kt == 0) {
            #pragma unroll
            for (int pl = 0; pl < 2; ++pl)
                #pragma unroll
                for (int ks = 0; ks < 4; ++ks) {
                    uint32_t ad = sb + (wq * 16 + (lane & 15)) * QROW
                                + pl * 128 + ks * 32 + (lane >> 4) * 16;
                    LDM4(qa[pl][ks], ad);
                }
        }

        uint32_t sKb = sb + SK_OFF + st * SK_SZ;
        uint32_t sVb = sb + SV_OFF + st * SV_SZ;

        // ---- S = Q K^T -----------------------------------------------------
        float sacc[8][4];
        #pragma unroll
        for (int fn = 0; fn < 8; ++fn)
            #pragma unroll
            for (int r = 0; r < 4; ++r) sacc[fn][r] = 0.f;

        #pragma unroll
        for (int fn = 0; fn < 8; ++fn) {
            #pragma unroll
            for (int ks = 0; ks < 4; ++ks) {
                uint32_t ba = sKb + (fn * 8 + g) * QROW + ks * 32 + cq * 4;
                uint32_t bhf[2], bmf[2];
                bhf[0] = lds32(ba);        bhf[1] = lds32(ba + 16);
                bmf[0] = lds32(ba + 128);  bmf[1] = lds32(ba + 144);
                MMA16816(sacc[fn], qa[0][ks], bhf);
                MMA16816(sacc[fn], qa[0][ks], bmf);
                MMA16816(sacc[fn], qa[1][ks], bhf);
            }
        }

        // ---- mask + online softmax ------------------------------------------
        int k0 = kt * 64;
        int r0 = q0 + wq * 16 + g;
        if (k0 + 63 > q0 + wq * 16) {
            #pragma unroll
            for (int fn = 0; fn < 8; ++fn) {
                int col = k0 + fn * 8 + 2 * cq;
                if (col     > r0)     sacc[fn][0] = -1e30f;
                if (col + 1 > r0)     sacc[fn][1] = -1e30f;
                if (col     > r0 + 8) sacc[fn][2] = -1e30f;
                if (col + 1 > r0 + 8) sacc[fn][3] = -1e30f;
            }
        }
        float mx0 = -1e30f, mx1 = -1e30f;
        #pragma unroll
        for (int fn = 0; fn < 8; ++fn) {
            mx0 = fmaxf(mx0, fmaxf(sacc[fn][0], sacc[fn][1]));
            mx1 = fmaxf(mx1, fmaxf(sacc[fn][2], sacc[fn][3]));
        }
        mx0 = fmaxf(mx0, __shfl_xor_sync(0xffffffffu, mx0, 1));
        mx0 = fmaxf(mx0, __shfl_xor_sync(0xffffffffu, mx0, 2));
        mx1 = fmaxf(mx1, __shfl_xor_sync(0xffffffffu, mx1, 1));
        mx1 = fmaxf(mx1, __shfl_xor_sync(0xffffffffu, mx1, 2));
        float mn0 = fmaxf(m0, mx0), mn1 = fmaxf(m1, mx1);
        float corr0 = __expf(m0 - mn0), corr1 = __expf(m1 - mn1);
        m0 = mn0; m1 = mn1;

        float rs0 = 0.f, rs1 = 0.f;
        uint32_t pah[4][4], pam[4][4];
        #pragma unroll
        for (int k2 = 0; k2 < 4; ++k2) {
            #pragma unroll
            for (int half = 0; half < 2; ++half) {
                int fn = k2 * 2 + half;
                float p0 = __expf(sacc[fn][0] - m0);
                float p1 = __expf(sacc[fn][1] - m0);
                float p2 = __expf(sacc[fn][2] - m1);
                float p3 = __expf(sacc[fn][3] - m1);
                rs0 += p0 + p1; rs1 += p2 + p3;
                float h0 = __bfloat162float(__float2bfloat16(p0));
                float h1 = __bfloat162float(__float2bfloat16(p1));
                float h2 = __bfloat162float(__float2bfloat16(p2));
                float h3 = __bfloat162float(__float2bfloat16(p3));
                pah[k2][half*2+0] = pack_bf16x2(p1, p0);
                pah[k2][half*2+1] = pack_bf16x2(p3, p2);
                pam[k2][half*2+0] = pack_bf16x2(p1 - h1, p0 - h0);
                pam[k2][half*2+1] = pack_bf16x2(p3 - h3, p2 - h2);
            }
        }
        rs0 += __shfl_xor_sync(0xffffffffu, rs0, 1);
        rs0 += __shfl_xor_sync(0xffffffffu, rs0, 2);
        rs1 += __shfl_xor_sync(0xffffffffu, rs1, 1);
        rs1 += __shfl_xor_sync(0xffffffffu, rs1, 2);
        l0 = l0 * corr0 + rs0;
        l1 = l1 * corr1 + rs1;

        // ---- O = O*corr + P V ------------------------------------------------
        #pragma unroll
        for (int fo = 0; fo < 8; ++fo) {
            oacc[fo][0] *= corr0; oacc[fo][1] *= corr0;
            oacc[fo][2] *= corr1; oacc[fo][3] *= corr1;
        }
        #pragma unroll
        for (int fo = 0; fo < 8; ++fo) {
            #pragma unroll
            for (int k2 = 0; k2 < 4; ++k2) {
                uint32_t ba = sVb + (fo * 8 + g) * VROW + k2 * 32 + cq * 4;
                uint32_t vhf[2], vmf[2];
                vhf[0] = lds32(ba);                 vhf[1] = lds32(ba + 16);
                vmf[0] = lds32(ba + 64 * VROW);     vmf[1] = lds32(ba + 64 * VROW + 16);
                MMA16816(oacc[fo], pah[k2], vhf);
                MMA16816(oacc[fo], pah[k2], vmf);
                MMA16816(oacc[fo], pam[k2], vhf);
            }
        }
        __syncthreads();
    }

    float inv0 = 1.f / l0, inv1 = 1.f / l1;
    int b = bh >> 4, h = bh & 15;
    int r0 = q0 + wq * 16 + g;
    #pragma unroll
    for (int fo = 0; fo < 8; ++fo) {
        int col = h * 64 + fo * 8 + 2 * cq;
        float2 w0, w1;
        w0.x = oacc[fo][0] * inv0; w0.y = oacc[fo][1] * inv0;
        w1.x = oacc[fo][2] * inv1; w1.y = oacc[fo][3] * inv1;
        *(float2*)(O + (size_t)(b * TT + r0) * CC + col) = w0;
        *(float2*)(O + (size_t)(b * TT + r0 + 8) * CC + col) = w1;
    }
}

// ------------------------- host launch --------------------------------------
extern "C" void kernel_launch(void* const* d_in, const int* in_sizes, int n_in,
                              void* d_out, int out_size) {
    const float* x      = (const float*)d_in[0];
    const float* w_attn = (const float*)d_in[2];
    const float* b_attn = (const float*)d_in[3];
    const float* a_attn = (const float*)d_in[4];
    const float* w_proj = (const float*)d_in[5];
    const float* b_proj = (const float*)d_in[6];
    const float* a_proj = (const float*)d_in[7];
    float* out = (float*)d_out;

    void *qkv_, *ao_, *xsq_, *xsq2_, *ksqa_, *ksqp_;
    void *ah_, *am_, *bha_, *bma_, *bhp_, *bmp_, *qp_, *kp_, *vt_;
    cudaGetSymbolAddress(&qkv_,  g_qkv);
    cudaGetSymbolAddress(&ao_,   g_ao);
    cudaGetSymbolAddress(&xsq_,  g_xsq);
    cudaGetSymbolAddress(&xsq2_, g_xsq2);
    cudaGetSymbolAddress(&ksqa_, g_ksqA);
    cudaGetSymbolAddress(&ksqp_, g_ksqP);
    cudaGetSymbolAddress(&ah_,   g_Ah);
    cudaGetSymbolAddress(&am_,   g_Am);
    cudaGetSymbolAddress(&bha_,  g_BhA);
    cudaGetSymbolAddress(&bma_,  g_BmA);
    cudaGetSymbolAddress(&bhp_,  g_BhP);
    cudaGetSymbolAddress(&bmp_,  g_BmP);
    cudaGetSymbolAddress(&qp_,   g_Qp);
    cudaGetSymbolAddress(&kp_,   g_Kp);
    cudaGetSymbolAddress(&vt_,   g_Vt);
    float* qkv  = (float*)qkv_;
    float* ao   = (float*)ao_;
    float* xsq  = (float*)xsq_;
    float* xsq2 = (float*)xsq2_;
    float* ksqa = (float*)ksqa_;
    float* ksqp = (float*)ksqp_;
    __nv_bfloat16* Ah  = (__nv_bfloat16*)ah_;
    __nv_bfloat16* Am  = (__nv_bfloat16*)am_;
    __nv_bfloat16* BhA = (__nv_bfloat16*)bha_;
    __nv_bfloat16* BmA = (__nv_bfloat16*)bma_;
    __nv_bfloat16* BhP = (__nv_bfloat16*)bhp_;
    __nv_bfloat16* BmP = (__nv_bfloat16*)bmp_;
    __nv_bfloat16* Qp  = (__nv_bfloat16*)qp_;
    __nv_bfloat16* Kp  = (__nv_bfloat16*)kp_;
    __nv_bfloat16* Vt  = (__nv_bfloat16*)vt_;

    const int gemm_smem = 2 * GSTAGE;                        // 73728
    cudaFuncSetAttribute(gemm_mma_kernel,
                         cudaFuncAttributeMaxDynamicSharedMemorySize, gemm_smem);
    cudaFuncSetAttribute(flash_mma_kernel,
                         cudaFuncAttributeMaxDynamicSharedMemorySize, FSMEM);

    // zero ksq accumulators (atomics target)
    zero_kernel<<<(N_QKV + 255) / 256, 256>>>(ksqa, N_QKV);
    zero_kernel<<<(CC + 255) / 256, 256>>>(ksqp, CC);

    // weight transpose + split + fused colsq
    {
        dim3 gr(N_QKV / 32, KK / 32), bl(32, 8);
        transpose_split_kernel<<<gr, bl>>>(w_attn, BhA, BmA, ksqa, N_QKV);
    }
    {
        dim3 gr(CC / 32, KK / 32), bl(32, 8);
        transpose_split_kernel<<<gr, bl>>>(w_proj, BhP, BmP, ksqp, CC);
    }

    // x split + fused rowsq
    split2_kernel<<<MM, 256>>>(x, Ah, Am, xsq);

    // GEMM1 + YAT -> qkv
    {
        dim3 grid(N_QKV / 128, MM / 128);
        gemm_mma_kernel<<<grid, 256, gemm_smem>>>(Ah, Am, BhA, BmA, b_attn, xsq,
                                                  ksqa, a_attn, qkv, N_QKV,
                                                  (float)N_QKV);
    }

    // RoPE + bf16 split + V transpose
    {
        dim3 grid(TT / 64, BH);
        rotary2_kernel<<<grid, 256>>>(qkv, Qp, Kp, Vt);
    }

    // flash attention (tensor cores) -> ao
    {
        dim3 grid(TT / FQ, BH);
        flash_mma_kernel<<<grid, 256, FSMEM>>>(Qp, Kp, Vt, ao);
    }

    // ao split + fused rowsq
    split2_kernel<<<MM, 256>>>(ao, Ah, Am, xsq2);

    // GEMM2 + YAT -> out
    {
        dim3 grid(CC / 128, MM / 128);
        gemm_mma_kernel<<<grid, 256, gemm_smem>>>(Ah, Am, BhP, BmP, b_proj, xsq2,
                                                  ksqp, a_proj, out, CC,
                                                  (float)CC);
    }
}

// round 5
// speedup vs baseline: 2.6286x; 1.1428x over previous
#include <cuda_runtime.h>
#include <cuda_bf16.h>
#include <math.h>
#include <stdint.h>

// Problem constants
#define BB 2
#define TT 2048
#define CC 1024
#define HH 16
#define DD 64
#define MM (BB*TT)          // 4096
#define N_QKV (3*CC)        // 3072
#define KK CC               // GEMM K = 1024
#define BH (BB*HH)          // 32
#define EPSY 1e-6f

// ------------------------- scratch (device globals) -----------------------
__device__ float g_qkv[(size_t)MM * N_QKV];
__device__ float g_xsq[MM];
__device__ float g_xsq2[MM];
__device__ float g_ksqA[N_QKV];
__device__ float g_ksqP[CC];
__device__ __nv_bfloat16 g_Ah[(size_t)MM * KK];
__device__ __nv_bfloat16 g_Am[(size_t)MM * KK];
__device__ __nv_bfloat16 g_BhA[(size_t)N_QKV * KK];
__device__ __nv_bfloat16 g_BmA[(size_t)N_QKV * KK];
__device__ __nv_bfloat16 g_BhP[(size_t)CC * KK];
__device__ __nv_bfloat16 g_BmP[(size_t)CC * KK];
// flash operands: Qp/Kp [bh][t][hi(64)|mid(64)] bf16; Vt [bh][plane(2)][d(64)][T]
__device__ __nv_bfloat16 g_Qp[(size_t)BH * TT * 128];
__device__ __nv_bfloat16 g_Kp[(size_t)BH * TT * 128];
__device__ __nv_bfloat16 g_Vt[(size_t)BH * 128 * TT];

// ------------------------- PTX helpers ------------------------------------
__device__ __forceinline__ uint32_t smem_u32(const void* p) {
    uint32_t a;
    asm("{ .reg .u64 t; cvta.to.shared.u64 t, %1; cvt.u32.u64 %0, t; }"
        : "=r"(a) : "l"(p));
    return a;
}
__device__ __forceinline__ void cp16(uint32_t dst, const void* src) {
    asm volatile("cp.async.cg.shared.global [%0], [%1], 16;" :: "r"(dst), "l"(src) : "memory");
}
#define CP_COMMIT() asm volatile("cp.async.commit_group;" ::: "memory")
#define CP_WAIT(n)  asm volatile("cp.async.wait_group %0;" :: "n"(n) : "memory")

#define LDM4(r0, r1, r2, r3, addr) \
    asm volatile("ldmatrix.sync.aligned.m8n8.x4.shared.b16 {%0,%1,%2,%3}, [%4];" \
        : "=r"(r0), "=r"(r1), "=r"(r2), "=r"(r3) : "r"(addr))

#define MMA16816(d, a, b) \
    asm volatile("mma.sync.aligned.m16n8k16.row.col.f32.bf16.bf16.f32 " \
        "{%0,%1,%2,%3}, {%4,%5,%6,%7}, {%8,%9}, {%0,%1,%2,%3};" \
        : "+f"((d)[0]), "+f"((d)[1]), "+f"((d)[2]), "+f"((d)[3]) \
        : "r"((a)[0]), "r"((a)[1]), "r"((a)[2]), "r"((a)[3]), \
          "r"((b)[0]), "r"((b)[1]))

// packs {hi, lo} fp32 -> bf16x2 (first source is upper half)
__device__ __forceinline__ uint32_t pack_bf16x2(float hi, float lo) {
    uint32_t r;
    asm("cvt.rn.bf16x2.f32 %0, %1, %2;" : "=r"(r) : "f"(hi), "f"(lo));
    return r;
}

// ------------------------- prep kernels -----------------------------------
// bf16x2 split + fused row sum-of-squares (one block == one 1024-float row)
__global__ void split2_kernel(const float* __restrict__ A,
                              __nv_bfloat16* __restrict__ H,
                              __nv_bfloat16* __restrict__ Mp,
                              float* __restrict__ xsq) {
    __shared__ float red[8];
    int row = blockIdx.x, tid = threadIdx.x;
    size_t i = (size_t)row * 256 + tid;
    float4 v = ((const float4*)A)[i];
    __nv_bfloat16 h0 = __float2bfloat16(v.x);
    __nv_bfloat16 h1 = __float2bfloat16(v.y);
    __nv_bfloat16 h2 = __float2bfloat16(v.z);
    __nv_bfloat16 h3 = __float2bfloat16(v.w);
    __nv_bfloat162* Hp = (__nv_bfloat162*)H;
    __nv_bfloat162* Mq = (__nv_bfloat162*)Mp;
    Hp[2*i]   = __nv_bfloat162(h0, h1);
    Hp[2*i+1] = __nv_bfloat162(h2, h3);
    Mq[2*i]   = __nv_bfloat162(__float2bfloat16(v.x - __bfloat162float(h0)),
                               __float2bfloat16(v.y - __bfloat162float(h1)));
    Mq[2*i+1] = __nv_bfloat162(__float2bfloat16(v.z - __bfloat162float(h2)),
                               __float2bfloat16(v.w - __bfloat162float(h3)));
    float s = v.x*v.x + v.y*v.y + v.z*v.z + v.w*v.w;
    #pragma unroll
    for (int off = 16; off > 0; off >>= 1)
        s += __shfl_xor_sync(0xffffffffu, s, off);
    if ((tid & 31) == 0) red[tid >> 5] = s;
    __syncthreads();
    if (tid == 0) {
        float t = 0.f;
        #pragma unroll
        for (int w = 0; w < 8; ++w) t += red[w];
        xsq[row] = t;
    }
}

__global__ void zero_kernel(float* __restrict__ a, int n) {
    int i = blockIdx.x * 256 + threadIdx.x;
    if (i < n) a[i] = 0.f;
}

// W [K,N] -> W^T split planes [N,K]; fused column sum-of-squares via atomics
__global__ void transpose_split_kernel(const float* __restrict__ W,
                                       __nv_bfloat16* __restrict__ Bh,
                                       __nv_bfloat16* __restrict__ Bm,
                                       float* __restrict__ ksq, int N) {
    __shared__ float tile[32][33];
    int n0 = blockIdx.x * 32, k0 = blockIdx.y * 32;
    int tx = threadIdx.x, ty = threadIdx.y;
    for (int j = ty; j < 32; j += 8)
        tile[j][tx] = W[(size_t)(k0 + j) * N + n0 + tx];
    __syncthreads();
    for (int j = ty; j < 32; j += 8) {
        float v = tile[tx][j];
        __nv_bfloat16 h = __float2bfloat16(v);
        __nv_bfloat16 m = __float2bfloat16(v - __bfloat162float(h));
        size_t o = (size_t)(n0 + j) * KK + k0 + tx;
        Bh[o] = h; Bm[o] = m;
        float sq = v * v;
        #pragma unroll
        for (int off = 16; off > 0; off >>= 1)
            sq += __shfl_xor_sync(0xffffffffu, sq, off);
        if (tx == 0) atomicAdd(&ksq[n0 + j], sq);
    }
}

// ------------------------- mma.sync GEMM + YAT epilogue -------------------
#define SROW 144
#define GTILE (128*SROW)
#define GSTAGE (2*GTILE)
#define GNKCH (KK/32)

__global__ __launch_bounds__(256, 1)
void gemm_mma_kernel(const __nv_bfloat16* __restrict__ Ah, const __nv_bfloat16* __restrict__ Am,
                     const __nv_bfloat16* __restrict__ Bh, const __nv_bfloat16* __restrict__ Bm,
                     const float* __restrict__ bias, const float* __restrict__ xsq,
                     const float* __restrict__ ksq, const float* __restrict__ alphap,
                     float* __restrict__ out, int N, float outf) {
    extern __shared__ char dsm[];
    uint32_t sbase = smem_u32(dsm);

    const int tid = threadIdx.x;
    const int lane = tid & 31;
    const int wid = tid >> 5;
    const int wm = wid >> 2;
    const int wn = wid & 3;
    const int m0 = blockIdx.y * 128;
    const int n0 = blockIdx.x * 128;
    const int l8 = lane & 7;
    const int lm = lane >> 3;

    const char* pAh = (const char*)Ah + (size_t)m0 * (KK*2);
    const char* pAm = (const char*)Am + (size_t)m0 * (KK*2);
    const char* pBh = (const char*)Bh + (size_t)n0 * (KK*2);
    const char* pBm = (const char*)Bm + (size_t)n0 * (KK*2);

    const int lplane = (tid >> 2) & 1;
    const int lchunk = tid & 3;

    #define LOAD_CHUNK(kc, st) do {                                           \
        size_t kb = (size_t)(kc) * 64 + (size_t)lchunk * 16;                  \
        uint32_t sb = sbase + (st) * GSTAGE;                                  \
        _Pragma("unroll")                                                     \
        for (int i = 0; i < 4; ++i) {                                         \
            int row = (tid >> 3) + i * 32;                                    \
            uint32_t doff = row * SROW + lplane * 64 + lchunk * 16;           \
            const char* sa = (lplane ? pAm : pAh) + (size_t)row * (KK*2) + kb;\
            const char* sbp = (lplane ? pBm : pBh) + (size_t)row * (KK*2) + kb;\
            cp16(sb + doff, sa);                                              \
            cp16(sb + GTILE + doff, sbp);                                     \
        }                                                                     \
        CP_COMMIT();                                                          \
    } while (0)

    float acc[4][4][4];
    #pragma unroll
    for (int i = 0; i < 4; ++i)
        #pragma unroll
        for (int j = 0; j < 4; ++j)
            #pragma unroll
            for (int r = 0; r < 4; ++r) acc[i][j][r] = 0.f;

    const int arow = lane & 15;
    const int akoff = (lane >> 4) * 16;

    LOAD_CHUNK(0, 0);

    for (int kc = 0; kc < GNKCH; ++kc) {
        int st = kc & 1;
        if (kc + 1 < GNKCH) {
            LOAD_CHUNK(kc + 1, st ^ 1);
            CP_WAIT(1);
        } else {
            CP_WAIT(0);
        }
        __syncthreads();

        uint32_t sA = sbase + st * GSTAGE;
        uint32_t sB = sA + GTILE;

        #pragma unroll
        for (int ks = 0; ks < 2; ++ks) {
            uint32_t a[2][4][4];
            #pragma unroll
            for (int pl = 0; pl < 2; ++pl)
                #pragma unroll
                for (int fm = 0; fm < 4; ++fm) {
                    uint32_t ad = sA + (wm*64 + fm*16 + arow) * SROW
                                + pl*64 + ks*32 + akoff;
                    LDM4(a[pl][fm][0], a[pl][fm][1], a[pl][fm][2], a[pl][fm][3], ad);
                }
            // b-frags via ldmatrix.x4: matrices = (fn, khalf); rows = n
            uint32_t b[2][4][2];
            #pragma unroll
            for (int pl = 0; pl < 2; ++pl)
                #pragma unroll
                for (int pr = 0; pr < 2; ++pr) {
                    uint32_t bd = sB + (wn*32 + (pr*2 + (lm >> 1))*8 + l8) * SROW
                                + pl*64 + ks*32 + (lm & 1)*16;
                    LDM4(b[pl][pr*2][0], b[pl][pr*2][1],
                         b[pl][pr*2+1][0], b[pl][pr*2+1][1], bd);
                }
            #pragma unroll
            for (int fm = 0; fm < 4; ++fm)
                #pragma unroll
                for (int fn = 0; fn < 4; ++fn) {
                    MMA16816(acc[fm][fn], a[0][fm], b[0][fn]);
                    MMA16816(acc[fm][fn], a[0][fm], b[1][fn]);
                    MMA16816(acc[fm][fn], a[1][fm], b[0][fn]);
                }
        }
        __syncthreads();
    }

    float alpha = *alphap;
    float scl = powf(sqrtf(outf) / logf(1.f + outf), alpha);
    int g = lane >> 2;
    int t2 = (lane & 3) * 2;

    #pragma unroll
    for (int fm = 0; fm < 4; ++fm) {
        int mA = m0 + wm*64 + fm*16 + g;
        float xsA = xsq[mA];
        float xsB = xsq[mA + 8];
        #pragma unroll
        for (int fn = 0; fn < 4; ++fn) {
            int col = n0 + wn*32 + fn*8 + t2;
            float k0v = ksq[col], k1v = ksq[col+1];
            float b0v = bias[col], b1v = bias[col+1];
            float d0 = acc[fm][fn][0], d1 = acc[fm][fn][1];
            float d2 = acc[fm][fn][2], d3 = acc[fm][fn][3];
            float2 o01, o23;
            o01.x = d0*d0 / (xsA + k0v - 2.f*d0 + EPSY) * scl + b0v;
            o01.y = d1*d1 / (xsA + k1v - 2.f*d1 + EPSY) * scl + b1v;
            o23.x = d2*d2 / (xsB + k0v - 2.f*d2 + EPSY) * scl + b0v;
            o23.y = d3*d3 / (xsB + k1v - 2.f*d3 + EPSY) * scl + b1v;
            *(float2*)(out + (size_t)mA * N + col) = o01;
            *(float2*)(out + (size_t)(mA + 8) * N + col) = o23;
        }
    }
    #undef LOAD_CHUNK
}

// ------------------------- RoPE + bf16x2 split + V transpose ---------------
__global__ __launch_bounds__(256)
void rotary2_kernel(const float* __restrict__ QKV,
                    __nv_bfloat16* __restrict__ Qp,
                    __nv_bfloat16* __restrict__ Kp,
                    __nv_bfloat16* __restrict__ Vt) {
    __shared__ __nv_bfloat16 vt[128][66];
    int tid = threadIdx.x;
    int bh = blockIdx.y;
    int t0 = blockIdx.x * 64;
    int b = bh >> 4, h = bh & 15;
    #pragma unroll
    for (int i = 0; i < 16; ++i) {
        int idx = tid + i * 256;
        int t = idx >> 6, d = idx & 63;
        int tg = t0 + t;
        size_t base = (size_t)(b * TT + tg) * N_QKV + h * 64;
        int dd = d & 31;
        bool hi = d >= 32;
        float freq = expf(-9.2103403719761836f * ((float)(2*dd) / 64.f));
        float sn, cs;
        sincosf((float)tg * freq, &sn, &cs);
        float q1 = QKV[base + dd],      q2 = QKV[base + dd + 32];
        float k1 = QKV[base + CC + dd], k2 = QKV[base + CC + dd + 32];
        float v  = QKV[base + 2*CC + d];
        float qv = (hi ? (q2*cs + q1*sn) : (q1*cs - q2*sn)) * 0.125f;
        float kv =  hi ? (k2*cs + k1*sn) : (k1*cs - k2*sn);
        __nv_bfloat16 qh = __float2bfloat16(qv);
        __nv_bfloat16 kh = __float2bfloat16(kv);
        size_t orow = ((size_t)bh * TT + tg) * 128;
        Qp[orow + d]      = qh;
        Qp[orow + 64 + d] = __float2bfloat16(qv - __bfloat162float(qh));
        Kp[orow + d]      = kh;
        Kp[orow + 64 + d] = __float2bfloat16(kv - __bfloat162float(kh));
        __nv_bfloat16 vh = __float2bfloat16(v);
        vt[d][t]      = vh;
        vt[64 + d][t] = __float2bfloat16(v - __bfloat162float(vh));
    }
    __syncthreads();
    uint32_t* outp = (uint32_t*)Vt;
    const uint32_t* vts = (const uint32_t*)&vt[0][0];
    #pragma unroll
    for (int i = 0; i < 16; ++i) {
        int idx = tid + i * 256;
        int r = idx >> 5, cpos = idx & 31;
        outp[((size_t)bh * 128 + r) * 1024 + (t0 >> 1) + cpos] = vts[r * 33 + cpos];
    }
}

// ------------------------- flash attention (mma.sync, bf16x2) --------------
// BQ=128, BK=64, 8 warps x 16 q rows. Q/K rows: [hi128|mid128|pad16]=272B.
// Vt rows (plane*64+d): 64 seq bf16 = 128B, padded stride 144B.
// Output fused: bf16 split planes (Ah/Am) + atomic row-sumsq into xsq2.
#define FQ 128
#define QROW 272
#define VROW 144
#define SQ_SZ (128*QROW)                 // 34816
#define SK_OFF SQ_SZ
#define SK_SZ (64*QROW)                  // 17408
#define SV_OFF (SK_OFF + 2*SK_SZ)        // 69632
#define SV_SZ (128*VROW)                 // 18432
#define FSMEM (SV_OFF + 2*SV_SZ)         // 106496

__global__ __launch_bounds__(256, 1)
void flash_mma_kernel(const __nv_bfloat16* __restrict__ Qp,
                      const __nv_bfloat16* __restrict__ Kp,
                      const __nv_bfloat16* __restrict__ Vt,
                      __nv_bfloat16* __restrict__ OH,
                      __nv_bfloat16* __restrict__ OM,
                      float* __restrict__ xsq2) {
    extern __shared__ char smf[];
    uint32_t sb = smem_u32(smf);
    int tid = threadIdx.x;
    int lane = tid & 31, wq = tid >> 5;
    int bh = blockIdx.x;
    int q0 = ((int)gridDim.y - 1 - (int)blockIdx.y) * FQ;   // big tiles first
    const int l8 = lane & 7, lm = lane >> 3;
    const char* Qg = (const char*)(Qp + ((size_t)bh * TT + q0) * 128);
    const char* Kg = (const char*)(Kp + (size_t)bh * TT * 128);
    const char* Vg = (const char*)(Vt + (size_t)bh * 128 * TT);

    // Q tile + KV tile 0 -> group 0
    #pragma unroll
    for (int i = 0; i < 8; ++i) {
        int idx = tid + i * 256; int r = idx >> 4, ch = idx & 15;
        cp16(sb + r * QROW + ch * 16, Qg + (size_t)r * 256 + ch * 16);
    }
    #pragma unroll
    for (int i = 0; i < 4; ++i) {
        int idx = tid + i * 256; int r = idx >> 4, ch = idx & 15;
        cp16(sb + SK_OFF + r * QROW + ch * 16, Kg + (size_t)r * 256 + ch * 16);
    }
    #pragma unroll
    for (int i = 0; i < 4; ++i) {
        int idx = tid + i * 256; int r = idx >> 3, ch = idx & 7;
        cp16(sb + SV_OFF + r * VROW + ch * 16, Vg + (size_t)r * 4096 + ch * 16);
    }
    CP_COMMIT();

    float oacc[8][4];
    #pragma unroll
    for (int fo = 0; fo < 8; ++fo)
        #pragma unroll
        for (int r = 0; r < 4; ++r) oacc[fo][r] = 0.f;
    uint32_t qa[2][4][4];
    float l0 = 0.f, l1 = 0.f, m0 = -1e30f, m1 = -1e30f;
    const int g = lane >> 2, cq = lane & 3;
    const int nkt = q0 / 64 + 2;

    for (int kt = 0; kt < nkt; ++kt) {
        int st = kt & 1;
        if (kt + 1 < nkt) {
            int sn = st ^ 1, k0n = (kt + 1) * 64;
            #pragma unroll
            for (int i = 0; i < 4; ++i) {
                int idx = tid + i * 256; int r = idx >> 4, ch = idx & 15;
                cp16(sb + SK_OFF + sn * SK_SZ + r * QROW + ch * 16,
                     Kg + (size_t)(k0n + r) * 256 + ch * 16);
            }
            #pragma unroll
            for (int i = 0; i < 4; ++i) {
                int idx = tid + i * 256; int r = idx >> 3, ch = idx & 7;
                cp16(sb + SV_OFF + sn * SV_SZ + r * VROW + ch * 16,
                     Vg + (size_t)r * 4096 + (size_t)k0n * 2 + ch * 16);
            }
            CP_COMMIT();
            CP_WAIT(1);
        } else {
            CP_WAIT(0);
        }
        __syncthreads();

        if (kt == 0) {
            #pragma unroll
            for (int pl = 0; pl < 2; ++pl)
                #pragma unroll
                for (int ks = 0; ks < 4; ++ks) {
                    uint32_t ad = sb + (wq * 16 + (lane & 15)) * QROW
                                + pl * 128 + ks * 32 + (lane >> 4) * 16;
                    LDM4(qa[pl][ks][0], qa[pl][ks][1], qa[pl][ks][2], qa[pl][ks][3], ad);
                }
        }

        uint32_t sKb = sb + SK_OFF + st * SK_SZ;
        uint32_t sVb = sb + SV_OFF + st * SV_SZ;

        // ---- S = Q K^T (K b-frags via ldmatrix.x4) ---------------------------
        float sacc[8][4];
        #pragma unroll
        for (int fn = 0; fn < 8; ++fn)
            #pragma unroll
            for (int r = 0; r < 4; ++r) sacc[fn][r] = 0.f;

        #pragma unroll
        for (int ks = 0; ks < 4; ++ks) {
            uint32_t kh[8][2], km[8][2];
            #pragma unroll
            for (int pr = 0; pr < 4; ++pr) {
                uint32_t base = sKb + ((pr*2 + (lm >> 1))*8 + l8) * QROW
                              + ks*32 + (lm & 1)*16;
                LDM4(kh[pr*2][0], kh[pr*2][1], kh[pr*2+1][0], kh[pr*2+1][1], base);
                LDM4(km[pr*2][0], km[pr*2][1], km[pr*2+1][0], km[pr*2+1][1], base + 128);
            }
            #pragma unroll
            for (int fn = 0; fn < 8; ++fn) {
                MMA16816(sacc[fn], qa[0][ks], kh[fn]);
                MMA16816(sacc[fn], qa[0][ks], km[fn]);
                MMA16816(sacc[fn], qa[1][ks], kh[fn]);
            }
        }

        // ---- mask + online softmax ------------------------------------------
        int k0 = kt * 64;
        int r0q = q0 + wq * 16 + g;
        if (k0 + 63 > q0 + wq * 16) {
            #pragma unroll
            for (int fn = 0; fn < 8; ++fn) {
                int col = k0 + fn * 8 + 2 * cq;
                if (col     > r0q)     sacc[fn][0] = -1e30f;
                if (col + 1 > r0q)     sacc[fn][1] = -1e30f;
                if (col     > r0q + 8) sacc[fn][2] = -1e30f;
                if (col + 1 > r0q + 8) sacc[fn][3] = -1e30f;
            }
        }
        float mx0 = -1e30f, mx1 = -1e30f;
        #pragma unroll
        for (int fn = 0; fn < 8; ++fn) {
            mx0 = fmaxf(mx0, fmaxf(sacc[fn][0], sacc[fn][1]));
            mx1 = fmaxf(mx1, fmaxf(sacc[fn][2], sacc[fn][3]));
        }
        mx0 = fmaxf(mx0, __shfl_xor_sync(0xffffffffu, mx0, 1));
        mx0 = fmaxf(mx0, __shfl_xor_sync(0xffffffffu, mx0, 2));
        mx1 = fmaxf(mx1, __shfl_xor_sync(0xffffffffu, mx1, 1));
        mx1 = fmaxf(mx1, __shfl_xor_sync(0xffffffffu, mx1, 2));
        float mn0 = fmaxf(m0, mx0), mn1 = fmaxf(m1, mx1);
        float corr0 = __expf(m0 - mn0), corr1 = __expf(m1 - mn1);
        m0 = mn0; m1 = mn1;

        float rs0 = 0.f, rs1 = 0.f;
        uint32_t pah[4][4], pam[4][4];
        #pragma unroll
        for (int k2 = 0; k2 < 4; ++k2) {
            #pragma unroll
            for (int half = 0; half < 2; ++half) {
                int fn = k2 * 2 + half;
                float p0 = __expf(sacc[fn][0] - m0);
                float p1 = __expf(sacc[fn][1] - m0);
                float p2 = __expf(sacc[fn][2] - m1);
                float p3 = __expf(sacc[fn][3] - m1);
                rs0 += p0 + p1; rs1 += p2 + p3;
                float h0 = __bfloat162float(__float2bfloat16(p0));
                float h1 = __bfloat162float(__float2bfloat16(p1));
                float h2 = __bfloat162float(__float2bfloat16(p2));
                float h3 = __bfloat162float(__float2bfloat16(p3));
                pah[k2][half*2+0] = pack_bf16x2(p1, p0);
                pah[k2][half*2+1] = pack_bf16x2(p3, p2);
                pam[k2][half*2+0] = pack_bf16x2(p1 - h1, p0 - h0);
                pam[k2][half*2+1] = pack_bf16x2(p3 - h3, p2 - h2);
            }
        }
        rs0 += __shfl_xor_sync(0xffffffffu, rs0, 1);
        rs0 += __shfl_xor_sync(0xffffffffu, rs0, 2);
        rs1 += __shfl_xor_sync(0xffffffffu, rs1, 1);
        rs1 += __shfl_xor_sync(0xffffffffu, rs1, 2);
        l0 = l0 * corr0 + rs0;
        l1 = l1 * corr1 + rs1;

        // ---- O = O*corr + P V (V b-frags via ldmatrix.x4) --------------------
        #pragma unroll
        for (int fo = 0; fo < 8; ++fo) {
            oacc[fo][0] *= corr0; oacc[fo][1] *= corr0;
            oacc[fo][2] *= corr1; oacc[fo][3] *= corr1;
        }
        #pragma unroll
        for (int k2 = 0; k2 < 4; ++k2) {
            uint32_t vh[8][2], vm[8][2];
            #pragma unroll
            for (int pr = 0; pr < 4; ++pr) {
                uint32_t base = sVb + ((pr*2 + (lm >> 1))*8 + l8) * VROW
                              + k2*32 + (lm & 1)*16;
                LDM4(vh[pr*2][0], vh[pr*2][1], vh[pr*2+1][0], vh[pr*2+1][1], base);
                LDM4(vm[pr*2][0], vm[pr*2][1], vm[pr*2+1][0], vm[pr*2+1][1],
                     base + 64 * VROW);
            }
            #pragma unroll
            for (int fo = 0; fo < 8; ++fo) {
                MMA16816(oacc[fo], pah[k2], vh[fo]);
                MMA16816(oacc[fo], pah[k2], vm[fo]);
                MMA16816(oacc[fo], pam[k2], vh[fo]);
            }
        }
        __syncthreads();
    }

    // ---- fused epilogue: bf16 split planes + atomic row-sumsq ---------------
    float inv0 = 1.f / l0, inv1 = 1.f / l1;
    int b = bh >> 4, h = bh & 15;
    int r0q = q0 + wq * 16 + g;
    size_t row0 = (size_t)(b * TT + r0q);
    float s0 = 0.f, s1 = 0.f;
    #pragma unroll
    for (int fo = 0; fo < 8; ++fo) {
        int col = h * 64 + fo * 8 + 2 * cq;
        float w00 = oacc[fo][0] * inv0, w01 = oacc[fo][1] * inv0;
        float w10 = oacc[fo][2] * inv1, w11 = oacc[fo][3] * inv1;
        s0 += w00*w00 + w01*w01;
        s1 += w10*w10 + w11*w11;
        float h00 = __bfloat162float(__float2bfloat16(w00));
        float h01 = __bfloat162float(__float2bfloat16(w01));
        float h10 = __bfloat162float(__float2bfloat16(w10));
        float h11 = __bfloat162float(__float2bfloat16(w11));
        *(uint32_t*)((char*)OH + (row0 * KK + col) * 2) = pack_bf16x2(w01, w00);
        *(uint32_t*)((char*)OM + (row0 * KK + col) * 2) = pack_bf16x2(w01 - h01, w00 - h00);
        *(uint32_t*)((char*)OH + ((row0 + 8) * KK + col) * 2) = pack_bf16x2(w11, w10);
        *(uint32_t*)((char*)OM + ((row0 + 8) * KK + col) * 2) = pack_bf16x2(w11 - h11, w10 - h10);
    }
    s0 += __shfl_xor_sync(0xffffffffu, s0, 1);
    s0 += __shfl_xor_sync(0xffffffffu, s0, 2);
    s1 += __shfl_xor_sync(0xffffffffu, s1, 1);
    s1 += __shfl_xor_sync(0xffffffffu, s1, 2);
    if (cq == 0) {
        atomicAdd(&xsq2[row0], s0);
        atomicAdd(&xsq2[row0 + 8], s1);
    }
}

// ------------------------- host launch --------------------------------------
extern "C" void kernel_launch(void* const* d_in, const int* in_sizes, int n_in,
                              void* d_out, int out_size) {
    const float* x      = (const float*)d_in[0];
    const float* w_attn = (const float*)d_in[2];
    const float* b_attn = (const float*)d_in[3];
    const float* a_attn = (const float*)d_in[4];
    const float* w_proj = (const float*)d_in[5];
    const float* b_proj = (const float*)d_in[6];
    const float* a_proj = (const float*)d_in[7];
    float* out = (float*)d_out;

    void *qkv_, *xsq_, *xsq2_, *ksqa_, *ksqp_;
    void *ah_, *am_, *bha_, *bma_, *bhp_, *bmp_, *qp_, *kp_, *vt_;
    cudaGetSymbolAddress(&qkv_,  g_qkv);
    cudaGetSymbolAddress(&xsq_,  g_xsq);
    cudaGetSymbolAddress(&xsq2_, g_xsq2);
    cudaGetSymbolAddress(&ksqa_, g_ksqA);
    cudaGetSymbolAddress(&ksqp_, g_ksqP);
    cudaGetSymbolAddress(&ah_,   g_Ah);
    cudaGetSymbolAddress(&am_,   g_Am);
    cudaGetSymbolAddress(&bha_,  g_BhA);
    cudaGetSymbolAddress(&bma_,  g_BmA);
    cudaGetSymbolAddress(&bhp_,  g_BhP);
    cudaGetSymbolAddress(&bmp_,  g_BmP);
    cudaGetSymbolAddress(&qp_,   g_Qp);
    cudaGetSymbolAddress(&kp_,   g_Kp);
    cudaGetSymbolAddress(&vt_,   g_Vt);
    float* qkv  = (float*)qkv_;
    float* xsq  = (float*)xsq_;
    float* xsq2 = (float*)xsq2_;
    float* ksqa = (float*)ksqa_;
    float* ksqp = (float*)ksqp_;
    __nv_bfloat16* Ah  = (__nv_bfloat16*)ah_;
    __nv_bfloat16* Am  = (__nv_bfloat16*)am_;
    __nv_bfloat16* BhA = (__nv_bfloat16*)bha_;
    __nv_bfloat16* BmA = (__nv_bfloat16*)bma_;
    __nv_bfloat16* BhP = (__nv_bfloat16*)bhp_;
    __nv_bfloat16* BmP = (__nv_bfloat16*)bmp_;
    __nv_bfloat16* Qp  = (__nv_bfloat16*)qp_;
    __nv_bfloat16* Kp  = (__nv_bfloat16*)kp_;
    __nv_bfloat16* Vt  = (__nv_bfloat16*)vt_;

    const int gemm_smem = 2 * GSTAGE;                        // 73728
    cudaFuncSetAttribute(gemm_mma_kernel,
                         cudaFuncAttributeMaxDynamicSharedMemorySize, gemm_smem);
    cudaFuncSetAttribute(flash_mma_kernel,
                         cudaFuncAttributeMaxDynamicSharedMemorySize, FSMEM);

    // zero accumulators for atomic reductions
    zero_kernel<<<(N_QKV + 255) / 256, 256>>>(ksqa, N_QKV);
    zero_kernel<<<(CC + 255) / 256, 256>>>(ksqp, CC);
    zero_kernel<<<(MM + 255) / 256, 256>>>(xsq2, MM);

    // weight transpose + split + fused colsq
    {
        dim3 gr(N_QKV / 32, KK / 32), bl(32, 8);
        transpose_split_kernel<<<gr, bl>>>(w_attn, BhA, BmA, ksqa, N_QKV);
    }
    {
        dim3 gr(CC / 32, KK / 32), bl(32, 8);
        transpose_split_kernel<<<gr, bl>>>(w_proj, BhP, BmP, ksqp, CC);
    }

    // x split + fused rowsq
    split2_kernel<<<MM, 256>>>(x, Ah, Am, xsq);

    // GEMM1 + YAT -> qkv
    {
        dim3 grid(N_QKV / 128, MM / 128);
        gemm_mma_kernel<<<grid, 256, gemm_smem>>>(Ah, Am, BhA, BmA, b_attn, xsq,
                                                  ksqa, a_attn, qkv, N_QKV,
                                                  (float)N_QKV);
    }

    // RoPE + bf16 split + V transpose
    {
        dim3 grid(TT / 64, BH);
        rotary2_kernel<<<grid, 256>>>(qkv, Qp, Kp, Vt);
    }

    // flash attention (tensor cores) -> Ah/Am split planes + xsq2
    {
        dim3 grid(BH, TT / FQ);
        flash_mma_kernel<<<grid, 256, FSMEM>>>(Qp, Kp, Vt, Ah, Am, xsq2);
    }

    // GEMM2 + YAT -> out
    {
        dim3 grid(CC / 128, MM / 128);
        gemm_mma_kernel<<<grid, 256, gemm_smem>>>(Ah, Am, BhP, BmP, b_proj, xsq2,
                                                  ksqp, a_proj, out, CC,
                                                  (float)CC);
    }
}

// round 6
// speedup vs baseline: 2.8064x; 1.0676x over previous
#include <cuda_runtime.h>
#include <cuda_bf16.h>
#include <math.h>
#include <stdint.h>

// Problem constants
#define BB 2
#define TT 2048
#define CC 1024
#define HH 16
#define DD 64
#define MM (BB*TT)          // 4096
#define N_QKV (3*CC)        // 3072
#define KK CC               // GEMM K = 1024
#define BH (BB*HH)          // 32
#define EPSY 1e-6f

// ------------------------- scratch (device globals) -----------------------
__device__ float g_qkv[(size_t)MM * N_QKV];
__device__ float g_xsq[MM];
__device__ float g_xsq2[MM];
__device__ float g_ksqA[N_QKV];
__device__ float g_ksqP[CC];
__device__ __nv_bfloat16 g_Ah[(size_t)MM * KK];
__device__ __nv_bfloat16 g_Am[(size_t)MM * KK];
__device__ __nv_bfloat16 g_BhA[(size_t)N_QKV * KK];
__device__ __nv_bfloat16 g_BmA[(size_t)N_QKV * KK];
__device__ __nv_bfloat16 g_BhP[(size_t)CC * KK];
__device__ __nv_bfloat16 g_BmP[(size_t)CC * KK];
// flash operands: Qp/Kp [bh][t][hi(64)|mid(64)] bf16; Vt [bh][plane(2)][d(64)][T]
__device__ __nv_bfloat16 g_Qp[(size_t)BH * TT * 128];
__device__ __nv_bfloat16 g_Kp[(size_t)BH * TT * 128];
__device__ __nv_bfloat16 g_Vt[(size_t)BH * 128 * TT];

// ------------------------- PTX helpers ------------------------------------
__device__ __forceinline__ uint32_t smem_u32(const void* p) {
    uint32_t a;
    asm("{ .reg .u64 t; cvta.to.shared.u64 t, %1; cvt.u32.u64 %0, t; }"
        : "=r"(a) : "l"(p));
    return a;
}
__device__ __forceinline__ void cp16(uint32_t dst, const void* src) {
    asm volatile("cp.async.cg.shared.global [%0], [%1], 16;" :: "r"(dst), "l"(src) : "memory");
}
#define CP_COMMIT() asm volatile("cp.async.commit_group;" ::: "memory")
#define CP_WAIT(n)  asm volatile("cp.async.wait_group %0;" :: "n"(n) : "memory")

#define LDM4(r0, r1, r2, r3, addr) \
    asm volatile("ldmatrix.sync.aligned.m8n8.x4.shared.b16 {%0,%1,%2,%3}, [%4];" \
        : "=r"(r0), "=r"(r1), "=r"(r2), "=r"(r3) : "r"(addr))

#define MMA16816(d, a, b) \
    asm volatile("mma.sync.aligned.m16n8k16.row.col.f32.bf16.bf16.f32 " \
        "{%0,%1,%2,%3}, {%4,%5,%6,%7}, {%8,%9}, {%0,%1,%2,%3};" \
        : "+f"((d)[0]), "+f"((d)[1]), "+f"((d)[2]), "+f"((d)[3]) \
        : "r"((a)[0]), "r"((a)[1]), "r"((a)[2]), "r"((a)[3]), \
          "r"((b)[0]), "r"((b)[1]))

// packs {hi, lo} fp32 -> bf16x2 (first source is upper half)
__device__ __forceinline__ uint32_t pack_bf16x2(float hi, float lo) {
    uint32_t r;
    asm("cvt.rn.bf16x2.f32 %0, %1, %2;" : "=r"(r) : "f"(hi), "f"(lo));
    return r;
}

// ------------------------- prep kernels -----------------------------------
__global__ void zero3_kernel(float* __restrict__ a, int na,
                             float* __restrict__ b, int nb,
                             float* __restrict__ c, int nc) {
    int i = blockIdx.x * 256 + threadIdx.x;
    if (i < na) a[i] = 0.f;
    if (i < nb) b[i] = 0.f;
    if (i < nc) c[i] = 0.f;
}

// bf16x2 split + fused row sum-of-squares (one block == one 1024-float row)
__global__ void split2_kernel(const float* __restrict__ A,
                              __nv_bfloat16* __restrict__ H,
                              __nv_bfloat16* __restrict__ Mp,
                              float* __restrict__ xsq) {
    __shared__ float red[8];
    int row = blockIdx.x, tid = threadIdx.x;
    size_t i = (size_t)row * 256 + tid;
    float4 v = ((const float4*)A)[i];
    __nv_bfloat16 h0 = __float2bfloat16(v.x);
    __nv_bfloat16 h1 = __float2bfloat16(v.y);
    __nv_bfloat16 h2 = __float2bfloat16(v.z);
    __nv_bfloat16 h3 = __float2bfloat16(v.w);
    __nv_bfloat162* Hp = (__nv_bfloat162*)H;
    __nv_bfloat162* Mq = (__nv_bfloat162*)Mp;
    Hp[2*i]   = __nv_bfloat162(h0, h1);
    Hp[2*i+1] = __nv_bfloat162(h2, h3);
    Mq[2*i]   = __nv_bfloat162(__float2bfloat16(v.x - __bfloat162float(h0)),
                               __float2bfloat16(v.y - __bfloat162float(h1)));
    Mq[2*i+1] = __nv_bfloat162(__float2bfloat16(v.z - __bfloat162float(h2)),
                               __float2bfloat16(v.w - __bfloat162float(h3)));
    float s = v.x*v.x + v.y*v.y + v.z*v.z + v.w*v.w;
    #pragma unroll
    for (int off = 16; off > 0; off >>= 1)
        s += __shfl_xor_sync(0xffffffffu, s, off);
    if ((tid & 31) == 0) red[tid >> 5] = s;
    __syncthreads();
    if (tid == 0) {
        float t = 0.f;
        #pragma unroll
        for (int w = 0; w < 8; ++w) t += red[w];
        xsq[row] = t;
    }
}

// W [K,N] -> W^T split planes [N,K]; fused column sum-of-squares via atomics
__global__ void transpose_split_kernel(const float* __restrict__ W,
                                       __nv_bfloat16* __restrict__ Bh,
                                       __nv_bfloat16* __restrict__ Bm,
                                       float* __restrict__ ksq, int N) {
    __shared__ float tile[32][33];
    int n0 = blockIdx.x * 32, k0 = blockIdx.y * 32;
    int tx = threadIdx.x, ty = threadIdx.y;
    for (int j = ty; j < 32; j += 8)
        tile[j][tx] = W[(size_t)(k0 + j) * N + n0 + tx];
    __syncthreads();
    for (int j = ty; j < 32; j += 8) {
        float v = tile[tx][j];
        __nv_bfloat16 h = __float2bfloat16(v);
        __nv_bfloat16 m = __float2bfloat16(v - __bfloat162float(h));
        size_t o = (size_t)(n0 + j) * KK + k0 + tx;
        Bh[o] = h; Bm[o] = m;
        float sq = v * v;
        #pragma unroll
        for (int off = 16; off > 0; off >>= 1)
            sq += __shfl_xor_sync(0xffffffffu, sq, off);
        if (tx == 0) atomicAdd(&ksq[n0 + j], sq);
    }
}

// ------------------------- mma.sync GEMM + YAT epilogue -------------------
// CTA 128(M)x256(N), 8 warps 2x4 -> warp tile 64x64. 3-stage cp.async.
#define SROW 144
#define ATILE (128*SROW)                 // 18432
#define BTILE (256*SROW)                 // 36864
#define GSTAGE (ATILE + BTILE)           // 55296
#define GNKCH (KK/32)                    // 32

__global__ __launch_bounds__(256, 1)
void gemm_mma_kernel(const __nv_bfloat16* __restrict__ Ah, const __nv_bfloat16* __restrict__ Am,
                     const __nv_bfloat16* __restrict__ Bh, const __nv_bfloat16* __restrict__ Bm,
                     const float* __restrict__ bias, const float* __restrict__ xsq,
                     const float* __restrict__ ksq, const float* __restrict__ alphap,
                     float* __restrict__ out, int N, float outf) {
    extern __shared__ char dsm[];
    uint32_t sbase = smem_u32(dsm);

    const int tid = threadIdx.x;
    const int lane = tid & 31;
    const int wid = tid >> 5;
    const int wm = wid >> 2;          // 0..1 -> m offset 64
    const int wn = wid & 3;           // 0..3 -> n offset 64
    const int m0 = blockIdx.y * 128;
    const int n0 = blockIdx.x * 256;
    const int l8 = lane & 7;
    const int lm = lane >> 3;

    const char* pAh = (const char*)Ah + (size_t)m0 * (KK*2);
    const char* pAm = (const char*)Am + (size_t)m0 * (KK*2);
    const char* pBh = (const char*)Bh + (size_t)n0 * (KK*2);
    const char* pBm = (const char*)Bm + (size_t)n0 * (KK*2);

    const int lplane = (tid >> 2) & 1;
    const int lchunk = tid & 3;

    #define LOAD_CHUNK(kc, st) do {                                           \
        size_t kb = (size_t)(kc) * 64 + (size_t)lchunk * 16;                  \
        uint32_t sbs = sbase + (st) * GSTAGE;                                 \
        uint32_t doff0 = (tid >> 3) * SROW + lplane * 64 + lchunk * 16;       \
        _Pragma("unroll")                                                     \
        for (int i = 0; i < 4; ++i) {                                         \
            int row = (tid >> 3) + i * 32;                                    \
            const char* sa = (lplane ? pAm : pAh) + (size_t)row * (KK*2) + kb;\
            cp16(sbs + doff0 + i * (32*SROW), sa);                            \
        }                                                                     \
        _Pragma("unroll")                                                     \
        for (int i = 0; i < 8; ++i) {                                         \
            int row = (tid >> 3) + i * 32;                                    \
            const char* sbp = (lplane ? pBm : pBh) + (size_t)row * (KK*2) + kb;\
            cp16(sbs + ATILE + doff0 + i * (32*SROW), sbp);                   \
        }                                                                     \
        CP_COMMIT();                                                          \
    } while (0)

    float acc[4][8][4];
    #pragma unroll
    for (int i = 0; i < 4; ++i)
        #pragma unroll
        for (int j = 0; j < 8; ++j)
            #pragma unroll
            for (int r = 0; r < 4; ++r) acc[i][j][r] = 0.f;

    const int arow = lane & 15;
    const int akoff = (lane >> 4) * 16;

    LOAD_CHUNK(0, 0);
    LOAD_CHUNK(1, 1);

    for (int kc = 0; kc < GNKCH; ++kc) {
        int st = kc - (kc / 3) * 3;
        if (kc + 2 < GNKCH) {
            int st2 = (kc + 2) - ((kc + 2) / 3) * 3;
            LOAD_CHUNK(kc + 2, st2);
            CP_WAIT(2);
        } else if (kc + 1 < GNKCH) {
            CP_WAIT(1);
        } else {
            CP_WAIT(0);
        }
        __syncthreads();

        uint32_t sA = sbase + st * GSTAGE;
        uint32_t sB = sA + ATILE;

        #pragma unroll
        for (int ks = 0; ks < 2; ++ks) {
            uint32_t a[2][4][4];
            #pragma unroll
            for (int pl = 0; pl < 2; ++pl)
                #pragma unroll
                for (int fm = 0; fm < 4; ++fm) {
                    uint32_t ad = sA + (wm*64 + fm*16 + arow) * SROW
                                + pl*64 + ks*32 + akoff;
                    LDM4(a[pl][fm][0], a[pl][fm][1], a[pl][fm][2], a[pl][fm][3], ad);
                }
            uint32_t b[2][8][2];
            #pragma unroll
            for (int pl = 0; pl < 2; ++pl)
                #pragma unroll
                for (int pr = 0; pr < 4; ++pr) {
                    uint32_t bd = sB + (wn*64 + (pr*2 + (lm >> 1))*8 + l8) * SROW
                                + pl*64 + ks*32 + (lm & 1)*16;
                    LDM4(b[pl][pr*2][0], b[pl][pr*2][1],
                         b[pl][pr*2+1][0], b[pl][pr*2+1][1], bd);
                }
            #pragma unroll
            for (int fm = 0; fm < 4; ++fm)
                #pragma unroll
                for (int fn = 0; fn < 8; ++fn) {
                    MMA16816(acc[fm][fn], a[0][fm], b[0][fn]);
                    MMA16816(acc[fm][fn], a[0][fm], b[1][fn]);
                    MMA16816(acc[fm][fn], a[1][fm], b[0][fn]);
                }
        }
        __syncthreads();
    }

    float alpha = *alphap;
    float scl = powf(sqrtf(outf) / logf(1.f + outf), alpha);
    int g = lane >> 2;
    int t2 = (lane & 3) * 2;

    #pragma unroll
    for (int fm = 0; fm < 4; ++fm) {
        int mA = m0 + wm*64 + fm*16 + g;
        float xsA = xsq[mA];
        float xsB = xsq[mA + 8];
        #pragma unroll
        for (int fn = 0; fn < 8; ++fn) {
            int col = n0 + wn*64 + fn*8 + t2;
            float k0v = ksq[col], k1v = ksq[col+1];
            float b0v = bias[col], b1v = bias[col+1];
            float d0 = acc[fm][fn][0], d1 = acc[fm][fn][1];
            float d2 = acc[fm][fn][2], d3 = acc[fm][fn][3];
            float2 o01, o23;
            o01.x = d0*d0 / (xsA + k0v - 2.f*d0 + EPSY) * scl + b0v;
            o01.y = d1*d1 / (xsA + k1v - 2.f*d1 + EPSY) * scl + b1v;
            o23.x = d2*d2 / (xsB + k0v - 2.f*d2 + EPSY) * scl + b0v;
            o23.y = d3*d3 / (xsB + k1v - 2.f*d3 + EPSY) * scl + b1v;
            *(float2*)(out + (size_t)mA * N + col) = o01;
            *(float2*)(out + (size_t)(mA + 8) * N + col) = o23;
        }
    }
    #undef LOAD_CHUNK
}

// ------------------------- RoPE + bf16x2 split + V transpose ---------------
__global__ __launch_bounds__(256)
void rotary2_kernel(const float* __restrict__ QKV,
                    __nv_bfloat16* __restrict__ Qp,
                    __nv_bfloat16* __restrict__ Kp,
                    __nv_bfloat16* __restrict__ Vt) {
    __shared__ __nv_bfloat16 vt[128][66];
    int tid = threadIdx.x;
    int bh = blockIdx.y;
    int t0 = blockIdx.x * 64;
    int b = bh >> 4, h = bh & 15;
    #pragma unroll
    for (int i = 0; i < 16; ++i) {
        int idx = tid + i * 256;
        int t = idx >> 6, d = idx & 63;
        int tg = t0 + t;
        size_t base = (size_t)(b * TT + tg) * N_QKV + h * 64;
        int dd = d & 31;
        bool hi = d >= 32;
        float freq = expf(-9.2103403719761836f * ((float)(2*dd) / 64.f));
        float sn, cs;
        sincosf((float)tg * freq, &sn, &cs);
        float q1 = QKV[base + dd],      q2 = QKV[base + dd + 32];
        float k1 = QKV[base + CC + dd], k2 = QKV[base + CC + dd + 32];
        float v  = QKV[base + 2*CC + d];
        float qv = (hi ? (q2*cs + q1*sn) : (q1*cs - q2*sn)) * 0.125f;
        float kv =  hi ? (k2*cs + k1*sn) : (k1*cs - k2*sn);
        __nv_bfloat16 qh = __float2bfloat16(qv);
        __nv_bfloat16 kh = __float2bfloat16(kv);
        size_t orow = ((size_t)bh * TT + tg) * 128;
        Qp[orow + d]      = qh;
        Qp[orow + 64 + d] = __float2bfloat16(qv - __bfloat162float(qh));
        Kp[orow + d]      = kh;
        Kp[orow + 64 + d] = __float2bfloat16(kv - __bfloat162float(kh));
        __nv_bfloat16 vh = __float2bfloat16(v);
        vt[d][t]      = vh;
        vt[64 + d][t] = __float2bfloat16(v - __bfloat162float(vh));
    }
    __syncthreads();
    uint32_t* outp = (uint32_t*)Vt;
    const uint32_t* vts = (const uint32_t*)&vt[0][0];
    #pragma unroll
    for (int i = 0; i < 16; ++i) {
        int idx = tid + i * 256;
        int r = idx >> 5, cpos = idx & 31;
        outp[((size_t)bh * 128 + r) * 1024 + (t0 >> 1) + cpos] = vts[r * 33 + cpos];
    }
}

// ------------------------- flash attention (mma.sync, bf16x2) --------------
// BQ=128, BK=128, 8 warps x 16 q rows. Q/K rows: [hi128|mid128|pad16]=272B.
// V smem rows (plane*64+d): 128 seq bf16 = 256B, padded to 272B.
#define FQ 128
#define QROW 272
#define VROW 272
#define SQ_SZ (128*QROW)                 // 34816
#define SK_OFF SQ_SZ
#define SK_SZ (128*QROW)                 // 34816
#define SV_OFF (SK_OFF + 2*SK_SZ)        // 104448
#define SV_SZ (128*VROW)                 // 34816
#define FSMEM (SV_OFF + 2*SV_SZ)         // 174080

__global__ __launch_bounds__(256, 1)
void flash_mma_kernel(const __nv_bfloat16* __restrict__ Qp,
                      const __nv_bfloat16* __restrict__ Kp,
                      const __nv_bfloat16* __restrict__ Vt,
                      __nv_bfloat16* __restrict__ OH,
                      __nv_bfloat16* __restrict__ OM,
                      float* __restrict__ xsq2) {
    extern __shared__ char smf[];
    uint32_t sb = smem_u32(smf);
    int tid = threadIdx.x;
    int lane = tid & 31, wq = tid >> 5;
    int bh = blockIdx.x;
    int qi = (int)gridDim.y - 1 - (int)blockIdx.y;          // big tiles first
    int q0 = qi * FQ;
    const int l8 = lane & 7, lm = lane >> 3;
    const char* Qg = (const char*)(Qp + ((size_t)bh * TT + q0) * 128);
    const char* Kg = (const char*)(Kp + (size_t)bh * TT * 128);
    const char* Vg = (const char*)(Vt + (size_t)bh * 128 * TT);

    // Q tile + KV tile 0 -> stage 0
    #pragma unroll
    for (int i = 0; i < 8; ++i) {
        int idx = tid + i * 256; int r = idx >> 4, ch = idx & 15;
        cp16(sb + r * QROW + ch * 16, Qg + (size_t)r * 256 + ch * 16);
    }
    #pragma unroll
    for (int i = 0; i < 8; ++i) {
        int idx = tid + i * 256; int r = idx >> 4, ch = idx & 15;
        cp16(sb + SK_OFF + r * QROW + ch * 16, Kg + (size_t)r * 256 + ch * 16);
    }
    #pragma unroll
    for (int i = 0; i < 8; ++i) {
        int idx = tid + i * 256; int r = idx >> 4, ch = idx & 15;
        cp16(sb + SV_OFF + r * VROW + ch * 16, Vg + (size_t)r * 4096 + ch * 16);
    }
    CP_COMMIT();

    float oacc[8][4];
    #pragma unroll
    for (int fo = 0; fo < 8; ++fo)
        #pragma unroll
        for (int r = 0; r < 4; ++r) oacc[fo][r] = 0.f;
    uint32_t qa[2][4][4];
    float l0 = 0.f, l1 = 0.f, m0 = -1e30f, m1 = -1e30f;
    const int g = lane >> 2, cq = lane & 3;
    const int nkt = qi + 1;

    for (int kt = 0; kt < nkt; ++kt) {
        int st = kt & 1;
        if (kt + 1 < nkt) {
            int sn = st ^ 1, k0n = (kt + 1) * FQ;
            #pragma unroll
            for (int i = 0; i < 8; ++i) {
                int idx = tid + i * 256; int r = idx >> 4, ch = idx & 15;
                cp16(sb + SK_OFF + sn * SK_SZ + r * QROW + ch * 16,
                     Kg + (size_t)(k0n + r) * 256 + ch * 16);
            }
            #pragma unroll
            for (int i = 0; i < 8; ++i) {
                int idx = tid + i * 256; int r = idx >> 4, ch = idx & 15;
                cp16(sb + SV_OFF + sn * SV_SZ + r * VROW + ch * 16,
                     Vg + (size_t)r * 4096 + (size_t)k0n * 2 + ch * 16);
            }
            CP_COMMIT();
            CP_WAIT(1);
        } else {
            CP_WAIT(0);
        }
        __syncthreads();

        if (kt == 0) {
            #pragma unroll
            for (int pl = 0; pl < 2; ++pl)
                #pragma unroll
                for (int ks = 0; ks < 4; ++ks) {
                    uint32_t ad = sb + (wq * 16 + (lane & 15)) * QROW
                                + pl * 128 + ks * 32 + (lane >> 4) * 16;
                    LDM4(qa[pl][ks][0], qa[pl][ks][1], qa[pl][ks][2], qa[pl][ks][3], ad);
                }
        }

        uint32_t sKb = sb + SK_OFF + st * SK_SZ;
        uint32_t sVb = sb + SV_OFF + st * SV_SZ;

        // ---- S = Q K^T over 128 columns (16 fn frags) -----------------------
        float sacc[16][4];
        #pragma unroll
        for (int fn = 0; fn < 16; ++fn)
            #pragma unroll
            for (int r = 0; r < 4; ++r) sacc[fn][r] = 0.f;

        #pragma unroll
        for (int ks = 0; ks < 4; ++ks) {
            #pragma unroll
            for (int half = 0; half < 2; ++half) {
                uint32_t kh[8][2], km[8][2];
                #pragma unroll
                for (int pr = 0; pr < 4; ++pr) {
                    uint32_t base = sKb
                        + (half*64 + (pr*2 + (lm >> 1))*8 + l8) * QROW
                        + ks*32 + (lm & 1)*16;
                    LDM4(kh[pr*2][0], kh[pr*2][1], kh[pr*2+1][0], kh[pr*2+1][1], base);
                    LDM4(km[pr*2][0], km[pr*2][1], km[pr*2+1][0], km[pr*2+1][1], base + 128);
                }
                #pragma unroll
                for (int f = 0; f < 8; ++f) {
                    MMA16816(sacc[half*8 + f], qa[0][ks], kh[f]);
                    MMA16816(sacc[half*8 + f], qa[0][ks], km[f]);
                    MMA16816(sacc[half*8 + f], qa[1][ks], kh[f]);
                }
            }
        }

        // ---- mask (diagonal tile only) + online softmax ----------------------
        int k0 = kt * FQ;
        int r0q = q0 + wq * 16 + g;
        if (kt == nkt - 1) {
            #pragma unroll
            for (int fn = 0; fn < 16; ++fn) {
                int col = k0 + fn * 8 + 2 * cq;
                if (col     > r0q)     sacc[fn][0] = -1e30f;
                if (col + 1 > r0q)     sacc[fn][1] = -1e30f;
                if (col     > r0q + 8) sacc[fn][2] = -1e30f;
                if (col + 1 > r0q + 8) sacc[fn][3] = -1e30f;
            }
        }
        float mx0 = -1e30f, mx1 = -1e30f;
        #pragma unroll
        for (int fn = 0; fn < 16; ++fn) {
            mx0 = fmaxf(mx0, fmaxf(sacc[fn][0], sacc[fn][1]));
            mx1 = fmaxf(mx1, fmaxf(sacc[fn][2], sacc[fn][3]));
        }
        mx0 = fmaxf(mx0, __shfl_xor_sync(0xffffffffu, mx0, 1));
        mx0 = fmaxf(mx0, __shfl_xor_sync(0xffffffffu, mx0, 2));
        mx1 = fmaxf(mx1, __shfl_xor_sync(0xffffffffu, mx1, 1));
        mx1 = fmaxf(mx1, __shfl_xor_sync(0xffffffffu, mx1, 2));
        float mn0 = fmaxf(m0, mx0), mn1 = fmaxf(m1, mx1);
        float corr0 = __expf(m0 - mn0), corr1 = __expf(m1 - mn1);
        m0 = mn0; m1 = mn1;

        float rs0 = 0.f, rs1 = 0.f;
        uint32_t pah[8][4], pam[8][4];
        #pragma unroll
        for (int k2 = 0; k2 < 8; ++k2) {
            #pragma unroll
            for (int half = 0; half < 2; ++half) {
                int fn = k2 * 2 + half;
                float p0 = __expf(sacc[fn][0] - m0);
                float p1 = __expf(sacc[fn][1] - m0);
                float p2 = __expf(sacc[fn][2] - m1);
                float p3 = __expf(sacc[fn][3] - m1);
                rs0 += p0 + p1; rs1 += p2 + p3;
                float h0 = __bfloat162float(__float2bfloat16(p0));
                float h1 = __bfloat162float(__float2bfloat16(p1));
                float h2 = __bfloat162float(__float2bfloat16(p2));
                float h3 = __bfloat162float(__float2bfloat16(p3));
                pah[k2][half*2+0] = pack_bf16x2(p1, p0);
                pah[k2][half*2+1] = pack_bf16x2(p3, p2);
                pam[k2][half*2+0] = pack_bf16x2(p1 - h1, p0 - h0);
                pam[k2][half*2+1] = pack_bf16x2(p3 - h3, p2 - h2);
            }
        }
        rs0 += __shfl_xor_sync(0xffffffffu, rs0, 1);
        rs0 += __shfl_xor_sync(0xffffffffu, rs0, 2);
        rs1 += __shfl_xor_sync(0xffffffffu, rs1, 1);
        rs1 += __shfl_xor_sync(0xffffffffu, rs1, 2);
        l0 = l0 * corr0 + rs0;
        l1 = l1 * corr1 + rs1;

        // ---- O = O*corr + P V ------------------------------------------------
        #pragma unroll
        for (int fo = 0; fo < 8; ++fo) {
            oacc[fo][0] *= corr0; oacc[fo][1] *= corr0;
            oacc[fo][2] *= corr1; oacc[fo][3] *= corr1;
        }
        #pragma unroll
        for (int k2 = 0; k2 < 8; ++k2) {
            uint32_t vh[8][2], vm[8][2];
            #pragma unroll
            for (int pr = 0; pr < 4; ++pr) {
                uint32_t base = sVb + ((pr*2 + (lm >> 1))*8 + l8) * VROW
                              + k2*32 + (lm & 1)*16;
                LDM4(vh[pr*2][0], vh[pr*2][1], vh[pr*2+1][0], vh[pr*2+1][1], base);
                LDM4(vm[pr*2][0], vm[pr*2][1], vm[pr*2+1][0], vm[pr*2+1][1],
                     base + 64 * VROW);
            }
            #pragma unroll
            for (int fo = 0; fo < 8; ++fo) {
                MMA16816(oacc[fo], pah[k2], vh[fo]);
                MMA16816(oacc[fo], pah[k2], vm[fo]);
                MMA16816(oacc[fo], pam[k2], vh[fo]);
            }
        }
        __syncthreads();
    }

    // ---- fused epilogue: bf16 split planes + atomic row-sumsq ---------------
    float inv0 = 1.f / l0, inv1 = 1.f / l1;
    int b = bh >> 4, h = bh & 15;
    int r0q = q0 + wq * 16 + g;
    size_t row0 = (size_t)(b * TT + r0q);
    float s0 = 0.f, s1 = 0.f;
    #pragma unroll
    for (int fo = 0; fo < 8; ++fo) {
        int col = h * 64 + fo * 8 + 2 * cq;
        float w00 = oacc[fo][0] * inv0, w01 = oacc[fo][1] * inv0;
        float w10 = oacc[fo][2] * inv1, w11 = oacc[fo][3] * inv1;
        s0 += w00*w00 + w01*w01;
        s1 += w10*w10 + w11*w11;
        float h00 = __bfloat162float(__float2bfloat16(w00));
        float h01 = __bfloat162float(__float2bfloat16(w01));
        float h10 = __bfloat162float(__float2bfloat16(w10));
        float h11 = __bfloat162float(__float2bfloat16(w11));
        *(uint32_t*)((char*)OH + (row0 * KK + col) * 2) = pack_bf16x2(w01, w00);
        *(uint32_t*)((char*)OM + (row0 * KK + col) * 2) = pack_bf16x2(w01 - h01, w00 - h00);
        *(uint32_t*)((char*)OH + ((row0 + 8) * KK + col) * 2) = pack_bf16x2(w11, w10);
        *(uint32_t*)((char*)OM + ((row0 + 8) * KK + col) * 2) = pack_bf16x2(w11 - h11, w10 - h10);
    }
    s0 += __shfl_xor_sync(0xffffffffu, s0, 1);
    s0 += __shfl_xor_sync(0xffffffffu, s0, 2);
    s1 += __shfl_xor_sync(0xffffffffu, s1, 1);
    s1 += __shfl_xor_sync(0xffffffffu, s1, 2);
    if (cq == 0) {
        atomicAdd(&xsq2[row0], s0);
        atomicAdd(&xsq2[row0 + 8], s1);
    }
}

// ------------------------- host launch --------------------------------------
extern "C" void kernel_launch(void* const* d_in, const int* in_sizes, int n_in,
                              void* d_out, int out_size) {
    const float* x      = (const float*)d_in[0];
    const float* w_attn = (const float*)d_in[2];
    const float* b_attn = (const float*)d_in[3];
    const float* a_attn = (const float*)d_in[4];
    const float* w_proj = (const float*)d_in[5];
    const float* b_proj = (const float*)d_in[6];
    const float* a_proj = (const float*)d_in[7];
    float* out = (float*)d_out;

    void *qkv_, *xsq_, *xsq2_, *ksqa_, *ksqp_;
    void *ah_, *am_, *bha_, *bma_, *bhp_, *bmp_, *qp_, *kp_, *vt_;
    cudaGetSymbolAddress(&qkv_,  g_qkv);
    cudaGetSymbolAddress(&xsq_,  g_xsq);
    cudaGetSymbolAddress(&xsq2_, g_xsq2);
    cudaGetSymbolAddress(&ksqa_, g_ksqA);
    cudaGetSymbolAddress(&ksqp_, g_ksqP);
    cudaGetSymbolAddress(&ah_,   g_Ah);
    cudaGetSymbolAddress(&am_,   g_Am);
    cudaGetSymbolAddress(&bha_,  g_BhA);
    cudaGetSymbolAddress(&bma_,  g_BmA);
    cudaGetSymbolAddress(&bhp_,  g_BhP);
    cudaGetSymbolAddress(&bmp_,  g_BmP);
    cudaGetSymbolAddress(&qp_,   g_Qp);
    cudaGetSymbolAddress(&kp_,   g_Kp);
    cudaGetSymbolAddress(&vt_,   g_Vt);
    float* qkv  = (float*)qkv_;
    float* xsq  = (float*)xsq_;
    float* xsq2 = (float*)xsq2_;
    float* ksqa = (float*)ksqa_;
    float* ksqp = (float*)ksqp_;
    __nv_bfloat16* Ah  = (__nv_bfloat16*)ah_;
    __nv_bfloat16* Am  = (__nv_bfloat16*)am_;
    __nv_bfloat16* BhA = (__nv_bfloat16*)bha_;
    __nv_bfloat16* BmA = (__nv_bfloat16*)bma_;
    __nv_bfloat16* BhP = (__nv_bfloat16*)bhp_;
    __nv_bfloat16* BmP = (__nv_bfloat16*)bmp_;
    __nv_bfloat16* Qp  = (__nv_bfloat16*)qp_;
    __nv_bfloat16* Kp  = (__nv_bfloat16*)kp_;
    __nv_bfloat16* Vt  = (__nv_bfloat16*)vt_;

    const int gemm_smem = 3 * GSTAGE;                        // 165888
    cudaFuncSetAttribute(gemm_mma_kernel,
                         cudaFuncAttributeMaxDynamicSharedMemorySize, gemm_smem);
    cudaFuncSetAttribute(flash_mma_kernel,
                         cudaFuncAttributeMaxDynamicSharedMemorySize, FSMEM);

    // zero all atomic accumulators in one launch
    zero3_kernel<<<(MM + 255) / 256, 256>>>(ksqa, N_QKV, ksqp, CC, xsq2, MM);

    // x split + fused rowsq
    split2_kernel<<<MM, 256>>>(x, Ah, Am, xsq);

    // weight transpose + split + fused colsq
    {
        dim3 gr(N_QKV / 32, KK / 32), bl(32, 8);
        transpose_split_kernel<<<gr, bl>>>(w_attn, BhA, BmA, ksqa, N_QKV);
    }
    {
        dim3 gr(CC / 32, KK / 32), bl(32, 8);
        transpose_split_kernel<<<gr, bl>>>(w_proj, BhP, BmP, ksqp, CC);
    }

    // GEMM1 + YAT -> qkv
    {
        dim3 grid(N_QKV / 256, MM / 128);
        gemm_mma_kernel<<<grid, 256, gemm_smem>>>(Ah, Am, BhA, BmA, b_attn, xsq,
                                                  ksqa, a_attn, qkv, N_QKV,
                                                  (float)N_QKV);
    }

    // RoPE + bf16 split + V transpose
    {
        dim3 grid(TT / 64, BH);
        rotary2_kernel<<<grid, 256>>>(qkv, Qp, Kp, Vt);
    }

    // flash attention (tensor cores) -> Ah/Am split planes + xsq2
    {
        dim3 grid(BH, TT / FQ);
        flash_mma_kernel<<<grid, 256, FSMEM>>>(Qp, Kp, Vt, Ah, Am, xsq2);
    }

    // GEMM2 + YAT -> out
    {
        dim3 grid(CC / 256, MM / 128);
        gemm_mma_kernel<<<grid, 256, gemm_smem>>>(Ah, Am, BhP, BmP, b_proj, xsq2,
                                                  ksqp, a_proj, out, CC,
                                                  (float)CC);
    }
}

// round 7
// speedup vs baseline: 2.8513x; 1.0160x over previous
#include <cuda_runtime.h>
#include <cuda_bf16.h>
#include <math.h>
#include <stdint.h>

// Problem constants
#define BB 2
#define TT 2048
#define CC 1024
#define HH 16
#define DD 64
#define MM (BB*TT)          // 4096
#define N_QKV (3*CC)        // 3072
#define KK CC               // GEMM K = 1024
#define BH (BB*HH)          // 32
#define EPSY 1e-6f

// ------------------------- scratch (device globals) -----------------------
__device__ float g_xsq[MM];
__device__ float g_xsq2[MM];
__device__ float g_ksqA[N_QKV];
__device__ float g_ksqP[CC];
__device__ float2 g_tbl[TT * 32];
__device__ __nv_bfloat16 g_Ah[(size_t)MM * KK];
__device__ __nv_bfloat16 g_Am[(size_t)MM * KK];
__device__ __nv_bfloat16 g_BhA[(size_t)N_QKV * KK];
__device__ __nv_bfloat16 g_BmA[(size_t)N_QKV * KK];
__device__ __nv_bfloat16 g_BhP[(size_t)CC * KK];
__device__ __nv_bfloat16 g_BmP[(size_t)CC * KK];
// flash operands: Qp/Kp/Vp [bh][t][hi(64)|mid(64)] bf16
__device__ __nv_bfloat16 g_Qp[(size_t)BH * TT * 128];
__device__ __nv_bfloat16 g_Kp[(size_t)BH * TT * 128];
__device__ __nv_bfloat16 g_Vp[(size_t)BH * TT * 128];

// ------------------------- PTX helpers ------------------------------------
__device__ __forceinline__ uint32_t smem_u32(const void* p) {
    uint32_t a;
    asm("{ .reg .u64 t; cvta.to.shared.u64 t, %1; cvt.u32.u64 %0, t; }"
        : "=r"(a) : "l"(p));
    return a;
}
__device__ __forceinline__ void cp16(uint32_t dst, const void* src) {
    asm volatile("cp.async.cg.shared.global [%0], [%1], 16;" :: "r"(dst), "l"(src) : "memory");
}
#define CP_COMMIT() asm volatile("cp.async.commit_group;" ::: "memory")
#define CP_WAIT(n)  asm volatile("cp.async.wait_group %0;" :: "n"(n) : "memory")

#define LDM4(r0, r1, r2, r3, addr) \
    asm volatile("ldmatrix.sync.aligned.m8n8.x4.shared.b16 {%0,%1,%2,%3}, [%4];" \
        : "=r"(r0), "=r"(r1), "=r"(r2), "=r"(r3) : "r"(addr))

#define LDM4T(r0, r1, r2, r3, addr) \
    asm volatile("ldmatrix.sync.aligned.m8n8.x4.trans.shared.b16 {%0,%1,%2,%3}, [%4];" \
        : "=r"(r0), "=r"(r1), "=r"(r2), "=r"(r3) : "r"(addr))

#define MMA16816(d, a, b) \
    asm volatile("mma.sync.aligned.m16n8k16.row.col.f32.bf16.bf16.f32 " \
        "{%0,%1,%2,%3}, {%4,%5,%6,%7}, {%8,%9}, {%0,%1,%2,%3};" \
        : "+f"((d)[0]), "+f"((d)[1]), "+f"((d)[2]), "+f"((d)[3]) \
        : "r"((a)[0]), "r"((a)[1]), "r"((a)[2]), "r"((a)[3]), \
          "r"((b)[0]), "r"((b)[1]))

// packs {hi, lo} fp32 -> bf16x2 (first source is upper half)
__device__ __forceinline__ uint32_t pack_bf16x2(float hi, float lo) {
    uint32_t r;
    asm("cvt.rn.bf16x2.f32 %0, %1, %2;" : "=r"(r) : "f"(hi), "f"(lo));
    return r;
}
// split-store a pair of adjacent cols (d even) into hi/mid planes of one row
__device__ __forceinline__ void store_pair(__nv_bfloat16* P, size_t rowo, int d,
                                           float a, float b) {
    float ha = __bfloat162float(__float2bfloat16(a));
    float hb = __bfloat162float(__float2bfloat16(b));
    *(uint32_t*)((char*)P + (rowo + d) * 2)      = pack_bf16x2(b, a);
    *(uint32_t*)((char*)P + (rowo + 64 + d) * 2) = pack_bf16x2(b - hb, a - ha);
}

// ------------------------- prep: zero accumulators + rope table ------------
__global__ void prep_kernel(float* __restrict__ ksqa, float* __restrict__ ksqp,
                            float* __restrict__ xsq2, float2* __restrict__ tbl) {
    int i = blockIdx.x * 256 + threadIdx.x;        // grid 256 -> 65536 threads
    if (i < N_QKV) ksqa[i] = 0.f;
    if (i < CC)    ksqp[i] = 0.f;
    if (i < MM)    xsq2[i] = 0.f;
    int t = i >> 5, dd = i & 31;
    float freq = expf(-9.2103403719761836f * ((float)(2*dd) / 64.f));
    float sn, cs;
    sincosf((float)t * freq, &sn, &cs);
    tbl[i] = make_float2(sn, cs);
}

// bf16x2 split + fused row sum-of-squares (one block == one 1024-float row)
__global__ void split2_kernel(const float* __restrict__ A,
                              __nv_bfloat16* __restrict__ H,
                              __nv_bfloat16* __restrict__ Mp,
                              float* __restrict__ xsq) {
    __shared__ float red[8];
    int row = blockIdx.x, tid = threadIdx.x;
    size_t i = (size_t)row * 256 + tid;
    float4 v = ((const float4*)A)[i];
    __nv_bfloat16 h0 = __float2bfloat16(v.x);
    __nv_bfloat16 h1 = __float2bfloat16(v.y);
    __nv_bfloat16 h2 = __float2bfloat16(v.z);
    __nv_bfloat16 h3 = __float2bfloat16(v.w);
    __nv_bfloat162* Hp = (__nv_bfloat162*)H;
    __nv_bfloat162* Mq = (__nv_bfloat162*)Mp;
    Hp[2*i]   = __nv_bfloat162(h0, h1);
    Hp[2*i+1] = __nv_bfloat162(h2, h3);
    Mq[2*i]   = __nv_bfloat162(__float2bfloat16(v.x - __bfloat162float(h0)),
                               __float2bfloat16(v.y - __bfloat162float(h1)));
    Mq[2*i+1] = __nv_bfloat162(__float2bfloat16(v.z - __bfloat162float(h2)),
                               __float2bfloat16(v.w - __bfloat162float(h3)));
    float s = v.x*v.x + v.y*v.y + v.z*v.z + v.w*v.w;
    #pragma unroll
    for (int off = 16; off > 0; off >>= 1)
        s += __shfl_xor_sync(0xffffffffu, s, off);
    if ((tid & 31) == 0) red[tid >> 5] = s;
    __syncthreads();
    if (tid == 0) {
        float t = 0.f;
        #pragma unroll
        for (int w = 0; w < 8; ++w) t += red[w];
        xsq[row] = t;
    }
}

// W [K,N] -> W^T split planes [N,K]; fused column sum-of-squares via atomics
__global__ void transpose_split_kernel(const float* __restrict__ W,
                                       __nv_bfloat16* __restrict__ Bh,
                                       __nv_bfloat16* __restrict__ Bm,
                                       float* __restrict__ ksq, int N) {
    __shared__ float tile[32][33];
    int n0 = blockIdx.x * 32, k0 = blockIdx.y * 32;
    int tx = threadIdx.x, ty = threadIdx.y;
    for (int j = ty; j < 32; j += 8)
        tile[j][tx] = W[(size_t)(k0 + j) * N + n0 + tx];
    __syncthreads();
    for (int j = ty; j < 32; j += 8) {
        float v = tile[tx][j];
        __nv_bfloat16 h = __float2bfloat16(v);
        __nv_bfloat16 m = __float2bfloat16(v - __bfloat162float(h));
        size_t o = (size_t)(n0 + j) * KK + k0 + tx;
        Bh[o] = h; Bm[o] = m;
        float sq = v * v;
        #pragma unroll
        for (int off = 16; off > 0; off >>= 1)
            sq += __shfl_xor_sync(0xffffffffu, sq, off);
        if (tx == 0) atomicAdd(&ksq[n0 + j], sq);
    }
}

// ------------------------- mma.sync GEMM + YAT epilogue -------------------
// CTA 128(M)x256(N), 8 warps 2x4 -> warp tile 64x64. 3-stage cp.async.
// MODE 0: YAT -> fp32 out.  MODE 1: YAT -> RoPE -> bf16 split planes Qp/Kp/Vp.
#define SROW 144
#define ATILE (128*SROW)                 // 18432
#define BTILE (256*SROW)                 // 36864
#define GSTAGE (ATILE + BTILE)           // 55296
#define GNKCH (KK/32)                    // 32

template<int MODE>
__global__ __launch_bounds__(256, 1)
void gemm_mma_kernel(const __nv_bfloat16* __restrict__ Ah, const __nv_bfloat16* __restrict__ Am,
                     const __nv_bfloat16* __restrict__ Bh, const __nv_bfloat16* __restrict__ Bm,
                     const float* __restrict__ bias, const float* __restrict__ xsq,
                     const float* __restrict__ ksq, const float* __restrict__ alphap,
                     float* __restrict__ out, int N, float outf,
                     __nv_bfloat16* __restrict__ Qp, __nv_bfloat16* __restrict__ Kp,
                     __nv_bfloat16* __restrict__ Vp, const float2* __restrict__ tbl) {
    extern __shared__ char dsm[];
    uint32_t sbase = smem_u32(dsm);

    const int tid = threadIdx.x;
    const int lane = tid & 31;
    const int wid = tid >> 5;
    const int wm = wid >> 2;          // 0..1 -> m offset 64
    const int wn = wid & 3;           // 0..3 -> n offset 64
    const int m0 = blockIdx.y * 128;
    const int n0 = blockIdx.x * 256;
    const int l8 = lane & 7;
    const int lm = lane >> 3;

    const char* pAh = (const char*)Ah + (size_t)m0 * (KK*2);
    const char* pAm = (const char*)Am + (size_t)m0 * (KK*2);
    const char* pBh = (const char*)Bh + (size_t)n0 * (KK*2);
    const char* pBm = (const char*)Bm + (size_t)n0 * (KK*2);

    const int lplane = (tid >> 2) & 1;
    const int lchunk = tid & 3;

    #define LOAD_CHUNK(kc, st) do {                                           \
        size_t kb = (size_t)(kc) * 64 + (size_t)lchunk * 16;                  \
        uint32_t sbs = sbase + (st) * GSTAGE;                                 \
        uint32_t doff0 = (tid >> 3) * SROW + lplane * 64 + lchunk * 16;       \
        _Pragma("unroll")                                                     \
        for (int i = 0; i < 4; ++i) {                                         \
            int row = (tid >> 3) + i * 32;                                    \
            const char* sa = (lplane ? pAm : pAh) + (size_t)row * (KK*2) + kb;\
            cp16(sbs + doff0 + i * (32*SROW), sa);                            \
        }                                                                     \
        _Pragma("unroll")                                                     \
        for (int i = 0; i < 8; ++i) {                                         \
            int row = (tid >> 3) + i * 32;                                    \
            const char* sbp = (lplane ? pBm : pBh) + (size_t)row * (KK*2) + kb;\
            cp16(sbs + ATILE + doff0 + i * (32*SROW), sbp);                   \
        }                                                                     \
        CP_COMMIT();                                                          \
    } while (0)

    float acc[4][8][4];
    #pragma unroll
    for (int i = 0; i < 4; ++i)
        #pragma unroll
        for (int j = 0; j < 8; ++j)
            #pragma unroll
            for (int r = 0; r < 4; ++r) acc[i][j][r] = 0.f;

    const int arow = lane & 15;
    const int akoff = (lane >> 4) * 16;

    LOAD_CHUNK(0, 0);
    LOAD_CHUNK(1, 1);

    for (int kc = 0; kc < GNKCH; ++kc) {
        int st = kc - (kc / 3) * 3;
        if (kc + 1 < GNKCH) { CP_WAIT(1); } else { CP_WAIT(0); }
        __syncthreads();
        if (kc + 2 < GNKCH) {
            int st2 = (kc + 2) - ((kc + 2) / 3) * 3;
            LOAD_CHUNK(kc + 2, st2);
        }

        uint32_t sA = sbase + st * GSTAGE;
        uint32_t sB = sA + ATILE;

        #pragma unroll
        for (int ks = 0; ks < 2; ++ks) {
            uint32_t a[2][4][4];
            #pragma unroll
            for (int pl = 0; pl < 2; ++pl)
                #pragma unroll
                for (int fm = 0; fm < 4; ++fm) {
                    uint32_t ad = sA + (wm*64 + fm*16 + arow) * SROW
                                + pl*64 + ks*32 + akoff;
                    LDM4(a[pl][fm][0], a[pl][fm][1], a[pl][fm][2], a[pl][fm][3], ad);
                }
            uint32_t b[2][8][2];
            #pragma unroll
            for (int pl = 0; pl < 2; ++pl)
                #pragma unroll
                for (int pr = 0; pr < 4; ++pr) {
                    uint32_t bd = sB + (wn*64 + (pr*2 + (lm >> 1))*8 + l8) * SROW
                                + pl*64 + ks*32 + (lm & 1)*16;
                    LDM4(b[pl][pr*2][0], b[pl][pr*2][1],
                         b[pl][pr*2+1][0], b[pl][pr*2+1][1], bd);
                }
            #pragma unroll
            for (int fm = 0; fm < 4; ++fm)
                #pragma unroll
                for (int fn = 0; fn < 8; ++fn) {
                    MMA16816(acc[fm][fn], a[0][fm], b[0][fn]);
                    MMA16816(acc[fm][fn], a[0][fm], b[1][fn]);
                    MMA16816(acc[fm][fn], a[1][fm], b[0][fn]);
                }
        }
        __syncthreads();
    }

    float alpha = *alphap;
    float scl = powf(sqrtf(outf) / logf(1.f + outf), alpha);
    int g = lane >> 2;
    int t2 = (lane & 3) * 2;

    #pragma unroll
    for (int fm = 0; fm < 4; ++fm) {
        int mA = m0 + wm*64 + fm*16 + g;
        float xsA = xsq[mA];
        float xsB = xsq[mA + 8];
        // YAT in place
        #pragma unroll
        for (int fn = 0; fn < 8; ++fn) {
            int col = n0 + wn*64 + fn*8 + t2;
            float k0v = ksq[col], k1v = ksq[col+1];
            float b0v = bias[col], b1v = bias[col+1];
            float d0 = acc[fm][fn][0], d1 = acc[fm][fn][1];
            float d2 = acc[fm][fn][2], d3 = acc[fm][fn][3];
            acc[fm][fn][0] = d0*d0 / (xsA + k0v - 2.f*d0 + EPSY) * scl + b0v;
            acc[fm][fn][1] = d1*d1 / (xsA + k1v - 2.f*d1 + EPSY) * scl + b1v;
            acc[fm][fn][2] = d2*d2 / (xsB + k0v - 2.f*d2 + EPSY) * scl + b0v;
            acc[fm][fn][3] = d3*d3 / (xsB + k1v - 2.f*d3 + EPSY) * scl + b1v;
        }
        if (MODE == 0) {
            #pragma unroll
            for (int fn = 0; fn < 8; ++fn) {
                int col = n0 + wn*64 + fn*8 + t2;
                *(float2*)(out + (size_t)mA * N + col)
                    = make_float2(acc[fm][fn][0], acc[fm][fn][1]);
                *(float2*)(out + (size_t)(mA+8) * N + col)
                    = make_float2(acc[fm][fn][2], acc[fm][fn][3]);
            }
        } else {
            int region = n0 >> 10;                       // 0 Q, 1 K, 2 V
            int hloc = ((n0 & 1023) + wn*64) >> 6;
            __nv_bfloat16* P = (region == 0) ? Qp : (region == 1) ? Kp : Vp;
            float qs = (region == 0) ? 0.125f : 1.f;
            #pragma unroll
            for (int half = 0; half < 2; ++half) {
                int mrow = mA + half*8;
                int t = mrow & (TT-1);
                int b = mrow >> 11;
                size_t rowo = ((size_t)(b*HH + hloc) * TT + t) * 128;
                if (region < 2) {
                    #pragma unroll
                    for (int fn = 0; fn < 4; ++fn) {
                        int dd = fn*8 + t2;
                        float4 sc = *(const float4*)(tbl + (t*32 + dd));
                        float x1a = acc[fm][fn][half*2]     * qs;
                        float x1b = acc[fm][fn][half*2+1]   * qs;
                        float x2a = acc[fm][fn+4][half*2]   * qs;
                        float x2b = acc[fm][fn+4][half*2+1] * qs;
                        store_pair(P, rowo, dd,
                                   x1a*sc.y - x2a*sc.x, x1b*sc.w - x2b*sc.z);
                        store_pair(P, rowo, dd + 32,
                                   x2a*sc.y + x1a*sc.x, x2b*sc.w + x1b*sc.z);
                    }
                } else {
                    #pragma unroll
                    for (int fn = 0; fn < 8; ++fn)
                        store_pair(P, rowo, fn*8 + t2,
                                   acc[fm][fn][half*2], acc[fm][fn][half*2+1]);
                }
            }
        }
    }
    #undef LOAD_CHUNK
}

// ------------------------- flash attention (mma.sync, bf16x2) --------------
// BQ=128, BK=128, 8 warps x 16 q rows. Q/K/V rows: [hi128|mid128|pad16]=272B.
#define FQ 128
#define QROW 272
#define VROW 272
#define SQ_SZ (128*QROW)                 // 34816
#define SK_OFF SQ_SZ
#define SK_SZ (128*QROW)
#define SV_OFF (SK_OFF + 2*SK_SZ)        // 104448
#define SV_SZ (128*VROW)
#define FSMEM (SV_OFF + 2*SV_SZ)         // 174080

__global__ __launch_bounds__(256, 1)
void flash_mma_kernel(const __nv_bfloat16* __restrict__ Qp,
                      const __nv_bfloat16* __restrict__ Kp,
                      const __nv_bfloat16* __restrict__ Vp,
                      __nv_bfloat16* __restrict__ OH,
                      __nv_bfloat16* __restrict__ OM,
                      float* __restrict__ xsq2) {
    extern __shared__ char smf[];
    uint32_t sb = smem_u32(smf);
    int tid = threadIdx.x;
    int lane = tid & 31, wq = tid >> 5;
    int bh = blockIdx.x;
    int qi = (int)gridDim.y - 1 - (int)blockIdx.y;          // big tiles first
    int q0 = qi * FQ;
    const int l8 = lane & 7, lm = lane >> 3;
    const char* Qg = (const char*)(Qp + ((size_t)bh * TT + q0) * 128);
    const char* Kg = (const char*)(Kp + (size_t)bh * TT * 128);
    const char* Vg = (const char*)(Vp + (size_t)bh * TT * 128);

    // Q tile + KV tile 0 -> stage 0
    #pragma unroll
    for (int i = 0; i < 8; ++i) {
        int idx = tid + i * 256; int r = idx >> 4, ch = idx & 15;
        cp16(sb + r * QROW + ch * 16, Qg + (size_t)r * 256 + ch * 16);
    }
    #pragma unroll
    for (int i = 0; i < 8; ++i) {
        int idx = tid + i * 256; int r = idx >> 4, ch = idx & 15;
        cp16(sb + SK_OFF + r * QROW + ch * 16, Kg + (size_t)r * 256 + ch * 16);
    }
    #pragma unroll
    for (int i = 0; i < 8; ++i) {
        int idx = tid + i * 256; int r = idx >> 4, ch = idx & 15;
        cp16(sb + SV_OFF + r * VROW + ch * 16, Vg + (size_t)r * 256 + ch * 16);
    }
    CP_COMMIT();

    float oacc[8][4];
    #pragma unroll
    for (int fo = 0; fo < 8; ++fo)
        #pragma unroll
        for (int r = 0; r < 4; ++r) oacc[fo][r] = 0.f;
    uint32_t qa[2][4][4];
    float l0 = 0.f, l1 = 0.f, m0 = -1e30f, m1 = -1e30f;
    const int g = lane >> 2, cq = lane & 3;
    const int nkt = qi + 1;

    for (int kt = 0; kt < nkt; ++kt) {
        int st = kt & 1;
        CP_WAIT(0);
        __syncthreads();
        if (kt + 1 < nkt) {
            int sn = st ^ 1, k0n = (kt + 1) * FQ;
            #pragma unroll
            for (int i = 0; i < 8; ++i) {
                int idx = tid + i * 256; int r = idx >> 4, ch = idx & 15;
                cp16(sb + SK_OFF + sn * SK_SZ + r * QROW + ch * 16,
                     Kg + (size_t)(k0n + r) * 256 + ch * 16);
            }
            #pragma unroll
            for (int i = 0; i < 8; ++i) {
                int idx = tid + i * 256; int r = idx >> 4, ch = idx & 15;
                cp16(sb + SV_OFF + sn * SV_SZ + r * VROW + ch * 16,
                     Vg + (size_t)(k0n + r) * 256 + ch * 16);
            }
            CP_COMMIT();
        }

        if (kt == 0) {
            #pragma unroll
            for (int pl = 0; pl < 2; ++pl)
                #pragma unroll
                for (int ks = 0; ks < 4; ++ks) {
                    uint32_t ad = sb + (wq * 16 + (lane & 15)) * QROW
                                + pl * 128 + ks * 32 + (lane >> 4) * 16;
                    LDM4(qa[pl][ks][0], qa[pl][ks][1], qa[pl][ks][2], qa[pl][ks][3], ad);
                }
        }

        uint32_t sKb = sb + SK_OFF + st * SK_SZ;
        uint32_t sVb = sb + SV_OFF + st * SV_SZ;

        // ---- S = Q K^T over 128 columns (16 fn frags) -----------------------
        float sacc[16][4];
        #pragma unroll
        for (int fn = 0; fn < 16; ++fn)
            #pragma unroll
            for (int r = 0; r < 4; ++r) sacc[fn][r] = 0.f;

        #pragma unroll
        for (int ks = 0; ks < 4; ++ks) {
            #pragma unroll
            for (int half = 0; half < 2; ++half) {
                uint32_t kh[8][2], km[8][2];
                #pragma unroll
                for (int pr = 0; pr < 4; ++pr) {
                    uint32_t base = sKb
                        + (half*64 + (pr*2 + (lm >> 1))*8 + l8) * QROW
                        + ks*32 + (lm & 1)*16;
                    LDM4(kh[pr*2][0], kh[pr*2][1], kh[pr*2+1][0], kh[pr*2+1][1], base);
                    LDM4(km[pr*2][0], km[pr*2][1], km[pr*2+1][0], km[pr*2+1][1], base + 128);
                }
                #pragma unroll
                for (int f = 0; f < 8; ++f) {
                    MMA16816(sacc[half*8 + f], qa[0][ks], kh[f]);
                    MMA16816(sacc[half*8 + f], qa[0][ks], km[f]);
                    MMA16816(sacc[half*8 + f], qa[1][ks], kh[f]);
                }
            }
        }

        // ---- mask (diagonal tile only) + online softmax ----------------------
        int k0 = kt * FQ;
        int r0q = q0 + wq * 16 + g;
        if (kt == nkt - 1) {
            #pragma unroll
            for (int fn = 0; fn < 16; ++fn) {
                int col = k0 + fn * 8 + 2 * cq;
                if (col     > r0q)     sacc[fn][0] = -1e30f;
                if (col + 1 > r0q)     sacc[fn][1] = -1e30f;
                if (col     > r0q + 8) sacc[fn][2] = -1e30f;
                if (col + 1 > r0q + 8) sacc[fn][3] = -1e30f;
            }
        }
        float mx0 = -1e30f, mx1 = -1e30f;
        #pragma unroll
        for (int fn = 0; fn < 16; ++fn) {
            mx0 = fmaxf(mx0, fmaxf(sacc[fn][0], sacc[fn][1]));
            mx1 = fmaxf(mx1, fmaxf(sacc[fn][2], sacc[fn][3]));
        }
        mx0 = fmaxf(mx0, __shfl_xor_sync(0xffffffffu, mx0, 1));
        mx0 = fmaxf(mx0, __shfl_xor_sync(0xffffffffu, mx0, 2));
        mx1 = fmaxf(mx1, __shfl_xor_sync(0xffffffffu, mx1, 1));
        mx1 = fmaxf(mx1, __shfl_xor_sync(0xffffffffu, mx1, 2));
        float mn0 = fmaxf(m0, mx0), mn1 = fmaxf(m1, mx1);
        float corr0 = __expf(m0 - mn0), corr1 = __expf(m1 - mn1);
        m0 = mn0; m1 = mn1;

        float rs0 = 0.f, rs1 = 0.f;
        uint32_t pah[8][4], pam[8][4];
        #pragma unroll
        for (int k2 = 0; k2 < 8; ++k2) {
            #pragma unroll
            for (int half = 0; half < 2; ++half) {
                int fn = k2 * 2 + half;
                float p0 = __expf(sacc[fn][0] - m0);
                float p1 = __expf(sacc[fn][1] - m0);
                float p2 = __expf(sacc[fn][2] - m1);
                float p3 = __expf(sacc[fn][3] - m1);
                rs0 += p0 + p1; rs1 += p2 + p3;
                float h0 = __bfloat162float(__float2bfloat16(p0));
                float h1 = __bfloat162float(__float2bfloat16(p1));
                float h2 = __bfloat162float(__float2bfloat16(p2));
                float h3 = __bfloat162float(__float2bfloat16(p3));
                pah[k2][half*2+0] = pack_bf16x2(p1, p0);
                pah[k2][half*2+1] = pack_bf16x2(p3, p2);
                pam[k2][half*2+0] = pack_bf16x2(p1 - h1, p0 - h0);
                pam[k2][half*2+1] = pack_bf16x2(p3 - h3, p2 - h2);
            }
        }
        rs0 += __shfl_xor_sync(0xffffffffu, rs0, 1);
        rs0 += __shfl_xor_sync(0xffffffffu, rs0, 2);
        rs1 += __shfl_xor_sync(0xffffffffu, rs1, 1);
        rs1 += __shfl_xor_sync(0xffffffffu, rs1, 2);
        l0 = l0 * corr0 + rs0;
        l1 = l1 * corr1 + rs1;

        // ---- O = O*corr + P V (V row-major, b-frags via ldmatrix.trans) ------
        #pragma unroll
        for (int fo = 0; fo < 8; ++fo) {
            oacc[fo][0] *= corr0; oacc[fo][1] *= corr0;
            oacc[fo][2] *= corr1; oacc[fo][3] *= corr1;
        }
        #pragma unroll
        for (int k2 = 0; k2 < 8; ++k2) {
            uint32_t vh[8][2], vm[8][2];
            #pragma unroll
            for (int pr = 0; pr < 4; ++pr) {
                uint32_t base = sVb + (k2*16 + (lm & 1)*8 + l8) * VROW
                              + (pr*2 + (lm >> 1)) * 16;
                LDM4T(vh[pr*2][0], vh[pr*2][1], vh[pr*2+1][0], vh[pr*2+1][1], base);
                LDM4T(vm[pr*2][0], vm[pr*2][1], vm[pr*2+1][0], vm[pr*2+1][1],
                      base + 128);
            }
            #pragma unroll
            for (int fo = 0; fo < 8; ++fo) {
                MMA16816(oacc[fo], pah[k2], vh[fo]);
                MMA16816(oacc[fo], pah[k2], vm[fo]);
                MMA16816(oacc[fo], pam[k2], vh[fo]);
            }
        }
    }

    // ---- fused epilogue: bf16 split planes + atomic row-sumsq ---------------
    float inv0 = 1.f / l0, inv1 = 1.f / l1;
    int b = bh >> 4, h = bh & 15;
    int r0q = q0 + wq * 16 + g;
    size_t row0 = (size_t)(b * TT + r0q);
    float s0 = 0.f, s1 = 0.f;
    #pragma unroll
    for (int fo = 0; fo < 8; ++fo) {
        int col = h * 64 + fo * 8 + 2 * cq;
        float w00 = oacc[fo][0] * inv0, w01 = oacc[fo][1] * inv0;
        float w10 = oacc[fo][2] * inv1, w11 = oacc[fo][3] * inv1;
        s0 += w00*w00 + w01*w01;
        s1 += w10*w10 + w11*w11;
        float h00 = __bfloat162float(__float2bfloat16(w00));
        float h01 = __bfloat162float(__float2bfloat16(w01));
        float h10 = __bfloat162float(__float2bfloat16(w10));
        float h11 = __bfloat162float(__float2bfloat16(w11));
        *(uint32_t*)((char*)OH + (row0 * KK + col) * 2) = pack_bf16x2(w01, w00);
        *(uint32_t*)((char*)OM + (row0 * KK + col) * 2) = pack_bf16x2(w01 - h01, w00 - h00);
        *(uint32_t*)((char*)OH + ((row0 + 8) * KK + col) * 2) = pack_bf16x2(w11, w10);
        *(uint32_t*)((char*)OM + ((row0 + 8) * KK + col) * 2) = pack_bf16x2(w11 - h11, w10 - h10);
    }
    s0 += __shfl_xor_sync(0xffffffffu, s0, 1);
    s0 += __shfl_xor_sync(0xffffffffu, s0, 2);
    s1 += __shfl_xor_sync(0xffffffffu, s1, 1);
    s1 += __shfl_xor_sync(0xffffffffu, s1, 2);
    if (cq == 0) {
        atomicAdd(&xsq2[row0], s0);
        atomicAdd(&xsq2[row0 + 8], s1);
    }
}

// ------------------------- host launch --------------------------------------
extern "C" void kernel_launch(void* const* d_in, const int* in_sizes, int n_in,
                              void* d_out, int out_size) {
    const float* x      = (const float*)d_in[0];
    const float* w_attn = (const float*)d_in[2];
    const float* b_attn = (const float*)d_in[3];
    const float* a_attn = (const float*)d_in[4];
    const float* w_proj = (const float*)d_in[5];
    const float* b_proj = (const float*)d_in[6];
    const float* a_proj = (const float*)d_in[7];
    float* out = (float*)d_out;

    void *xsq_, *xsq2_, *ksqa_, *ksqp_, *tbl_;
    void *ah_, *am_, *bha_, *bma_, *bhp_, *bmp_, *qp_, *kp_, *vp_;
    cudaGetSymbolAddress(&xsq_,  g_xsq);
    cudaGetSymbolAddress(&xsq2_, g_xsq2);
    cudaGetSymbolAddress(&ksqa_, g_ksqA);
    cudaGetSymbolAddress(&ksqp_, g_ksqP);
    cudaGetSymbolAddress(&tbl_,  g_tbl);
    cudaGetSymbolAddress(&ah_,   g_Ah);
    cudaGetSymbolAddress(&am_,   g_Am);
    cudaGetSymbolAddress(&bha_,  g_BhA);
    cudaGetSymbolAddress(&bma_,  g_BmA);
    cudaGetSymbolAddress(&bhp_,  g_BhP);
    cudaGetSymbolAddress(&bmp_,  g_BmP);
    cudaGetSymbolAddress(&qp_,   g_Qp);
    cudaGetSymbolAddress(&kp_,   g_Kp);
    cudaGetSymbolAddress(&vp_,   g_Vp);
    float* xsq  = (float*)xsq_;
    float* xsq2 = (float*)xsq2_;
    float* ksqa = (float*)ksqa_;
    float* ksqp = (float*)ksqp_;
    float2* tbl = (float2*)tbl_;
    __nv_bfloat16* Ah  = (__nv_bfloat16*)ah_;
    __nv_bfloat16* Am  = (__nv_bfloat16*)am_;
    __nv_bfloat16* BhA = (__nv_bfloat16*)bha_;
    __nv_bfloat16* BmA = (__nv_bfloat16*)bma_;
    __nv_bfloat16* BhP = (__nv_bfloat16*)bhp_;
    __nv_bfloat16* BmP = (__nv_bfloat16*)bmp_;
    __nv_bfloat16* Qp  = (__nv_bfloat16*)qp_;
    __nv_bfloat16* Kp  = (__nv_bfloat16*)kp_;
    __nv_bfloat16* Vp  = (__nv_bfloat16*)vp_;

    const int gemm_smem = 3 * GSTAGE;                        // 165888
    cudaFuncSetAttribute(gemm_mma_kernel<0>,
                         cudaFuncAttributeMaxDynamicSharedMemorySize, gemm_smem);
    cudaFuncSetAttribute(gemm_mma_kernel<1>,
                         cudaFuncAttributeMaxDynamicSharedMemorySize, gemm_smem);
    cudaFuncSetAttribute(flash_mma_kernel,
                         cudaFuncAttributeMaxDynamicSharedMemorySize, FSMEM);

    // zero accumulators + rope table
    prep_kernel<<<256, 256>>>(ksqa, ksqp, xsq2, tbl);

    // x split + fused rowsq
    split2_kernel<<<MM, 256>>>(x, Ah, Am, xsq);

    // weight transpose + split + fused colsq
    {
        dim3 gr(N_QKV / 32, KK / 32), bl(32, 8);
        transpose_split_kernel<<<gr, bl>>>(w_attn, BhA, BmA, ksqa, N_QKV);
    }
    {
        dim3 gr(CC / 32, KK / 32), bl(32, 8);
        transpose_split_kernel<<<gr, bl>>>(w_proj, BhP, BmP, ksqp, CC);
    }

    // GEMM1 + YAT + RoPE + split -> Qp/Kp/Vp (no fp32 qkv intermediate)
    {
        dim3 grid(N_QKV / 256, MM / 128);
        gemm_mma_kernel<1><<<grid, 256, gemm_smem>>>(Ah, Am, BhA, BmA, b_attn, xsq,
                                                     ksqa, a_attn, nullptr, N_QKV,
                                                     (float)N_QKV, Qp, Kp, Vp, tbl);
    }

    // flash attention (tensor cores) -> Ah/Am split planes + xsq2
    {
        dim3 grid(BH, TT / FQ);
        flash_mma_kernel<<<grid, 256, FSMEM>>>(Qp, Kp, Vp, Ah, Am, xsq2);
    }

    // GEMM2 + YAT -> out
    {
        dim3 grid(CC / 256, MM / 128);
        gemm_mma_kernel<0><<<grid, 256, gemm_smem>>>(Ah, Am, BhP, BmP, b_proj, xsq2,
                                                     ksqp, a_proj, out, CC,
                                                     (float)CC, nullptr, nullptr,
                                                     nullptr, nullptr);
    }
}